// round 14
// baseline (speedup 1.0000x reference)
#include <cuda_runtime.h>
#include <cuda_fp16.h>
#include <math.h>
#include <stdint.h>

// ---------------------------------------------------------------------------
// Problem constants
// ---------------------------------------------------------------------------
#define BSZ   64
#define IMG   128
#define CH    24
#define QD    11
#define AD    10
#define NN    64      // objects per image (8x8)
#define FD    26      // CH + 2 coords
#define HID   256
#define EPSV  1e-5f

// rn_mma geometry (fp16) — proven 512-thread configuration
#define M_CTA     128
#define SA        264            // half-element stride
#define WSLAB_B   32768
#define N_SLABS   12
#define DYN_RN    (2*WSLAB_B + M_CTA*SA*2)   // 133120

// ---------------------------------------------------------------------------
// Scratch
// ---------------------------------------------------------------------------
__device__ float  g_x1[BSZ*CH*64*64];
__device__ float  g_x2[BSZ*CH*32*32];
__device__ float  g_x3[BSZ*CH*16*16];
__device__ float  g_x4[BSZ*CH*8*8];
__device__ float  g_u [BSZ*NN*HID];
__device__ float  g_v [BSZ*NN*HID];
__device__ float  g_s [BSZ*HID];
__device__ float  g_gsum[BSZ*HID];    // zero-init at load; re-zeroed by last rn CTA
__device__ uint2  g_wf[3*16*32*32];
__device__ float  g_bnsum[4*CH];      // zero-init at load; re-zeroed by last rn CTA
__device__ float  g_bnsq [4*CH];
__device__ int    g_cnt[BSZ];         // per-image completion counters (self-resetting)

// ---------------------------------------------------------------------------
// Helpers
// ---------------------------------------------------------------------------
__device__ __forceinline__ uint32_t smem_u32(const void* p) {
    uint32_t a;
    asm("{ .reg .u64 t; cvta.to.shared.u64 t, %1; cvt.u32.u64 %0, t; }"
        : "=r"(a) : "l"(p));
    return a;
}
__device__ __forceinline__ void mma_f16(float* c, const uint32_t* a,
                                        uint32_t b0, uint32_t b1) {
    asm volatile(
        "mma.sync.aligned.m16n8k16.row.col.f32.f16.f16.f32 "
        "{%0,%1,%2,%3}, {%4,%5,%6,%7}, {%8,%9}, {%0,%1,%2,%3};"
        : "+f"(c[0]), "+f"(c[1]), "+f"(c[2]), "+f"(c[3])
        : "r"(a[0]), "r"(a[1]), "r"(a[2]), "r"(a[3]), "r"(b0), "r"(b1));
}
__device__ __forceinline__ void cp16(uint32_t dst, const void* src) {
    asm volatile("cp.async.cg.shared.global [%0], [%1], 16;"
                 :: "r"(dst), "l"(__cvta_generic_to_global(src)) : "memory");
}
#define CP_COMMIT() asm volatile("cp.async.commit_group;" ::: "memory")
#define CP_WAIT1()  asm volatile("cp.async.wait_group 1;" ::: "memory")
#define CP_WAIT0()  asm volatile("cp.async.wait_group 0;" ::: "memory")

__device__ __forceinline__ uint32_t pack_h2(float lo, float hi) {
    __half2 h = __floats2half2_rn(lo, hi);
    return *(uint32_t*)&h;
}

// ---------------------------------------------------------------------------
// Tiled conv (k=3,s=2,p=1) + inline input-BN + bias + ReLU + channel stats.
// Big buffers in DYNAMIC smem (planes, then weights at aligned offset).
// ---------------------------------------------------------------------------
template<int CI, int CO, int HIN, int HOUT, int TILE, int CPG, int HW_IN,
         bool APPLY, bool WFRAG>
__global__ void __launch_bounds__(TILE*TILE*CO/CPG)
conv_tile_kernel(const float* __restrict__ in,
                 const float* __restrict__ w,
                 const float* __restrict__ bias,
                 const float* __restrict__ sum_in,
                 const float* __restrict__ sq_in,
                 const float* __restrict__ bg_in,
                 const float* __restrict__ bb_in,
                 float* __restrict__ out,
                 float* __restrict__ sum_g,
                 float* __restrict__ sq_g,
                 const float* __restrict__ gw2,
                 const float* __restrict__ gw3,
                 const float* __restrict__ gw4,
                 uint2* __restrict__ wf) {
    constexpr int PW     = 2*TILE + 1;
    constexpr int PSZ    = PW*PW;
    constexpr int NPIX   = TILE*TILE;
    constexpr int NG     = CO/CPG;
    constexpr int NT     = NPIX*NG;
    constexpr int PL_PAD = (CI*PSZ + 3) & ~3;
    extern __shared__ float plS[];                   // planes + weights
    float* wS = plS + PL_PAD;                        // CI*CO*12 floats
    __shared__ float bS[CO];
    __shared__ float sci[CI], shi[CI];
    __shared__ float csum[CO], csq[CO];

    const int tid = threadIdx.x;
    for (int i = tid; i < CI*CO*9; i += NT) {
        int cico = i / 9, k = i - cico*9;
        int co = cico / CI, ci = cico - co*CI;
        wS[(ci*CO + co)*12 + k] = w[i];
    }
    if (tid < CO) { bS[tid] = bias[tid]; csum[tid] = 0.f; csq[tid] = 0.f; }
    if (tid < CI) {
        if (APPLY) {
            float cnt = (float)(BSZ * HW_IN);
            float m   = sum_in[tid] / cnt;
            float var = sq_in[tid] / cnt - m * m;
            float inv = rsqrtf(var + EPSV);
            float sc  = bg_in[tid] * inv;
            sci[tid] = sc;
            shi[tid] = bb_in[tid] - m * sc;
        } else { sci[tid] = 1.f; shi[tid] = 0.f; }
    }
    __syncthreads();

    constexpr int TPS = HOUT / TILE;
    const int bx = blockIdx.x;
    const int b  = bx / (TPS*TPS);
    const int tr = bx - b*(TPS*TPS);
    const int ty = (tr / TPS) * TILE;
    const int tx = (tr - (tr / TPS)*TPS) * TILE;
    const int iy0 = ty*2 - 1;
    const int ix0 = tx*2 - 1;

    for (int i = tid; i < CI*PSZ; i += NT) {
        int ci = i / PSZ;
        int r  = i - ci*PSZ;
        int ry = r / PW, rx = r - ry*PW;
        int gy = iy0 + ry, gx = ix0 + rx;
        float v = 0.f;
        if (gy >= 0 && gy < HIN && gx >= 0 && gx < HIN)
            v = in[((size_t)(b*CI + ci)*HIN + gy)*HIN + gx] * sci[ci] + shi[ci];
        plS[i] = v;
    }
    __syncthreads();

    const int pix = tid & (NPIX - 1);
    const int cg  = tid / NPIX;
    const int py  = pix / TILE;
    const int px  = pix - py*TILE;
    const int co0 = cg * CPG;

    float acc[CPG];
    #pragma unroll
    for (int cc = 0; cc < CPG; cc++) acc[cc] = 0.f;

    #pragma unroll 2
    for (int ci = 0; ci < CI; ci++) {
        const float* pl = plS + ci*PSZ + (2*py)*PW + 2*px;
        float win[9];
        #pragma unroll
        for (int dy = 0; dy < 3; dy++) {
            win[dy*3+0] = pl[dy*PW+0];
            win[dy*3+1] = pl[dy*PW+1];
            win[dy*3+2] = pl[dy*PW+2];
        }
        #pragma unroll
        for (int cc = 0; cc < CPG; cc++) {
            const float* wp = &wS[(ci*CO + co0 + cc)*12];
            const float4 w0 = *(const float4*)wp;
            const float4 w1 = *(const float4*)(wp + 4);
            const float  w8 = wp[8];
            acc[cc] += win[0]*w0.x + win[1]*w0.y + win[2]*w0.z
                     + win[3]*w0.w + win[4]*w1.x + win[5]*w1.y
                     + win[6]*w1.z + win[7]*w1.w + win[8]*w8;
        }
    }

    // epilogue: bias + relu + store + channel stats.
    constexpr int RW = (NPIX < 32) ? NPIX : 32;
    const int lane = tid & 31;
    #pragma unroll
    for (int cc = 0; cc < CPG; cc++) {
        int co = co0 + cc;
        float val = fmaxf(acc[cc] + bS[co], 0.f);
        out[((size_t)(b*CO + co)*HOUT + ty + py)*HOUT + tx + px] = val;
        float s = val, s2 = val*val;
        #pragma unroll
        for (int off = RW/2; off > 0; off >>= 1) {
            s  += __shfl_xor_sync(0xFFFFFFFFu, s,  off);
            s2 += __shfl_xor_sync(0xFFFFFFFFu, s2, off);
        }
        if ((lane & (RW - 1)) == 0) {
            atomicAdd(&csum[co], s);
            atomicAdd(&csq [co], s2);
        }
    }
    __syncthreads();
    if (tid < CO) {
        atomicAdd(&sum_g[tid], csum[tid]);
        atomicAdd(&sq_g [tid], csq [tid]);
    }

    if (WFRAG) {
        int gidx = blockIdx.x * NT + tid;
        if (gidx < 3*16384) {
            int l  = gidx >> 14;
            int r  = gidx & 16383;
            int k  = r >> 10;
            int jg = (r >> 5) & 31;
            int t  = r & 31;
            const float* g = (l == 0) ? gw2 : (l == 1) ? gw3 : gw4;
            int n  = jg*8 + (t >> 2);
            int kk = k*16 + 2*(t & 3);
            uint2 val;
            val.x = pack_h2(g[(size_t)kk*HID + n],     g[(size_t)(kk+1)*HID + n]);
            val.y = pack_h2(g[(size_t)(kk+8)*HID + n], g[(size_t)(kk+9)*HID + n]);
            wf[gidx] = val;
        }
    }
}

// dynamic smem sizes per instantiation
#define CONV1_DYN ((((3*33*33 + 3) & ~3) + 3*24*12) * 4)     // 16528
#define CONVN_DYN ((((24*17*17 + 3) & ~3) + 24*24*12) * 4)   // 55392
#define CONV4_DYN ((((24*9*9 + 3) & ~3) + 24*24*12) * 4)     // 35424 (<48KB)

// ---------------------------------------------------------------------------
// Launch #5: layer-1 factorization — 2 objects per block (512 thr),
// inline BN4 finalize; blocks handling n==0 also compute s.
// ---------------------------------------------------------------------------
__global__ void __launch_bounds__(512)
uv_kernel(const float* __restrict__ x4,
          const float* __restrict__ bnsum4,
          const float* __restrict__ bnsq4,
          const float* __restrict__ bg4,
          const float* __restrict__ bb4,
          const float* __restrict__ q,
          const float* __restrict__ gw1,
          const float* __restrict__ gb1,
          float* __restrict__ u, float* __restrict__ v,
          float* __restrict__ s) {
    __shared__ float o[2][FD];
    __shared__ float qv[QD];
    const int tid = threadIdx.x;
    const int sub = tid >> 8;
    const int c   = tid & 255;
    const int bn0 = blockIdx.x * 2;
    const int bn  = bn0 + sub;
    const int b   = bn >> 6, n = bn & 63;

    if (tid < 2*CH) {
        int ss = tid / CH, cc = tid - ss*CH;
        int bb_ = (bn0 + ss) >> 6, nn = (bn0 + ss) & 63;
        float cnt = (float)(BSZ * 64);
        float m   = bnsum4[cc] / cnt;
        float var = bnsq4[cc] / cnt - m * m;
        float inv = rsqrtf(var + EPSV);
        float sc  = bg4[cc] * inv;
        float sh  = bb4[cc] - m * sc;
        o[ss][cc] = x4[(size_t)(bb_*CH + cc)*64 + nn] * sc + sh;
    } else if (tid >= 256 && tid < 256 + 2) {
        int ss = tid - 256;
        int nn = (bn0 + ss) & 63;
        o[ss][CH]   = (float)(nn >> 3) * 0.125f;
        o[ss][CH+1] = (float)(nn & 7)  * 0.125f;
    } else if (tid >= 300 && tid < 300 + QD) {
        qv[tid - 300] = q[(bn0 >> 6)*QD + (tid - 300)];
    }
    __syncthreads();

    float us = 0.f, vs = 0.f;
    #pragma unroll
    for (int f = 0; f < FD; f++) {
        float ov = o[sub][f];
        us += ov * gw1[f*HID + c];
        vs += ov * gw1[(FD + f)*HID + c];
    }
    u[(size_t)bn*HID + c] = us;
    v[(size_t)bn*HID + c] = vs;

    if (n == 0 && sub == 0) {
        float sa = gb1[c];
        #pragma unroll
        for (int t = 0; t < QD; t++)
            sa += qv[t] * gw1[(2*FD + t)*HID + c];
        s[(size_t)b*HID + c] = sa;
    }
}

// ---------------------------------------------------------------------------
// Launch #6: tensor-core relational core (R10-proven 512-thread mainloop)
// + fused f_phi tail: the last CTA per image (completion counter) runs the
// 256->256->256->10 head inline and restores all accumulator invariants.
// ---------------------------------------------------------------------------
__global__ void __launch_bounds__(512, 1)
rn_mma_kernel(const float* __restrict__ u, const float* __restrict__ v,
              const float* __restrict__ sb, float* __restrict__ gsum,
              const uint2* __restrict__ wf,
              const float* __restrict__ gb2, const float* __restrict__ gb3,
              const float* __restrict__ gb4,
              const float* __restrict__ fw1, const float* __restrict__ fb1,
              const float* __restrict__ fw2, const float* __restrict__ fb2,
              const float* __restrict__ fw3, const float* __restrict__ fb3,
              float* __restrict__ out, int* __restrict__ cnt,
              float* __restrict__ bnsum_g, float* __restrict__ bnsq_g) {
    extern __shared__ char dyn[];
    __half* hAh = (__half*)(dyn + 2*WSLAB_B);
    const uint2* wbuf2 = (const uint2*)dyn;
    const uint32_t wsm = smem_u32(dyn);
    __shared__ float biasS[3*HID];
    __shared__ float colsum[HID];
    __shared__ int lastFlag;

    const int tid  = threadIdx.x;
    const int lane = tid & 31;
    const int warp = tid >> 5;
    const int mg   = warp & 3;
    const int ng   = warp >> 2;
    const int tig  = lane & 3;

    for (int i = tid; i < HID; i += 512) {
        biasS[i]         = gb2[i];
        biasS[HID + i]   = gb3[i];
        biasS[2*HID + i] = gb4[i];
    }
    if (tid < HID) colsum[tid] = 0.f;

    const int b  = blockIdx.x >> 5;
    const int i0 = (blockIdx.x & 31) * 2;
    {
        const int row = tid >> 2;
        const int c0  = (tid & 3) * 64;
        const int ii  = i0 + (row >> 6);
        const int jj  = row & 63;
        const float* up = u  + (size_t)(b*NN + ii) * HID;
        const float* vp = v  + (size_t)(b*NN + jj) * HID;
        const float* sp = sb + (size_t)b * HID;
        #pragma unroll
        for (int f = 0; f < 8; f++) {
            int c = c0 + f*8;
            float4 u0 = *(const float4*)(up + c);
            float4 v0 = *(const float4*)(vp + c);
            float4 s0 = *(const float4*)(sp + c);
            float4 u1 = *(const float4*)(up + c + 4);
            float4 v1 = *(const float4*)(vp + c + 4);
            float4 s1 = *(const float4*)(sp + c + 4);
            uint4 hq;
            hq.x = pack_h2(fmaxf(u0.x+v0.x+s0.x, 0.f), fmaxf(u0.y+v0.y+s0.y, 0.f));
            hq.y = pack_h2(fmaxf(u0.z+v0.z+s0.z, 0.f), fmaxf(u0.w+v0.w+s0.w, 0.f));
            hq.z = pack_h2(fmaxf(u1.x+v1.x+s1.x, 0.f), fmaxf(u1.y+v1.y+s1.y, 0.f));
            hq.w = pack_h2(fmaxf(u1.z+v1.z+s1.z, 0.f), fmaxf(u1.w+v1.w+s1.w, 0.f));
            *(uint4*)(hAh + row*SA + c) = hq;
        }
    }

    {
        const char* src = (const char*)wf;
        #pragma unroll
        for (int i = 0; i < 4; i++)
            cp16(wsm + (i*512 + tid)*16, src + (i*512 + tid)*16);
        CP_COMMIT();
    }

    float acc[2][8][4];

    #pragma unroll 1
    for (int sl = 0; sl < N_SLABS; sl++) {
        const int l   = sl >> 2;
        const int cur = sl & 1;
        __syncthreads();
        if (sl + 1 < N_SLABS) {
            const char* src = (const char*)wf + (size_t)(sl + 1) * WSLAB_B;
            uint32_t dst = wsm + (cur ^ 1) * WSLAB_B;
            #pragma unroll
            for (int i = 0; i < 4; i++)
                cp16(dst + (i*512 + tid)*16, src + (i*512 + tid)*16);
            CP_COMMIT();
            CP_WAIT1();
        } else {
            CP_WAIT0();
        }
        __syncthreads();

        if ((sl & 3) == 0) {
            #pragma unroll
            for (int mt = 0; mt < 2; mt++)
                #pragma unroll
                for (int j = 0; j < 8; j++)
                    #pragma unroll
                    for (int c = 0; c < 4; c++)
                        acc[mt][j][c] = 0.f;
        }

        const uint2* wslab = wbuf2 + cur * (WSLAB_B/8);
        const int kbase = (sl & 3) * 4;
        #pragma unroll
        for (int kk = 0; kk < 4; kk++) {
            const int kcol = (kbase + kk) * 16;
            uint32_t a[2][4];
            #pragma unroll
            for (int mt = 0; mt < 2; mt++) {
                int rA = mg*32 + mt*16 + (lane >> 2);
                const __half* base = hAh + rA*SA + kcol + 2*tig;
                a[mt][0] = *(const uint32_t*)(base);
                a[mt][1] = *(const uint32_t*)(base + 8*SA);
                a[mt][2] = *(const uint32_t*)(base + 8);
                a[mt][3] = *(const uint32_t*)(base + 8*SA + 8);
            }
            #pragma unroll
            for (int j = 0; j < 8; j++) {
                uint2 bb = wslab[(kk*32 + (ng*8 + j))*32 + lane];
                mma_f16(acc[0][j], a[0], bb.x, bb.y);
                mma_f16(acc[1][j], a[1], bb.x, bb.y);
            }
        }

        if ((sl & 3) == 3) {
            __syncthreads();
            if (l < 2) {
                const float* bl = biasS + l*HID;
                #pragma unroll
                for (int mt = 0; mt < 2; mt++) {
                    int rA = mg*32 + mt*16 + (lane >> 2);
                    #pragma unroll
                    for (int j = 0; j < 8; j++) {
                        int col = ng*64 + j*8 + 2*tig;
                        float b0 = bl[col], b1 = bl[col+1];
                        uint32_t lo = pack_h2(fmaxf(acc[mt][j][0] + b0, 0.f),
                                              fmaxf(acc[mt][j][1] + b1, 0.f));
                        uint32_t hi = pack_h2(fmaxf(acc[mt][j][2] + b0, 0.f),
                                              fmaxf(acc[mt][j][3] + b1, 0.f));
                        *(uint32_t*)(hAh + rA*SA + col)     = lo;
                        *(uint32_t*)(hAh + (rA+8)*SA + col) = hi;
                    }
                }
                __syncthreads();
            } else {
                const float* bl = biasS + 2*HID;
                #pragma unroll
                for (int j = 0; j < 8; j++) {
                    int col = ng*64 + j*8 + 2*tig;
                    float b0 = bl[col], b1 = bl[col+1];
                    float s0 = 0.f, s1 = 0.f;
                    #pragma unroll
                    for (int mt = 0; mt < 2; mt++) {
                        s0 += fmaxf(acc[mt][j][0] + b0, 0.f)
                            + fmaxf(acc[mt][j][2] + b0, 0.f);
                        s1 += fmaxf(acc[mt][j][1] + b1, 0.f)
                            + fmaxf(acc[mt][j][3] + b1, 0.f);
                    }
                    #pragma unroll
                    for (int off = 4; off < 32; off <<= 1) {
                        s0 += __shfl_xor_sync(0xFFFFFFFFu, s0, off);
                        s1 += __shfl_xor_sync(0xFFFFFFFFu, s1, off);
                    }
                    if (lane < 4) {
                        atomicAdd(&colsum[col],     s0);
                        atomicAdd(&colsum[col + 1], s1);
                    }
                }
            }
        }
    }

    __syncthreads();
    if (tid < HID) atomicAdd(&gsum[b*HID + tid], colsum[tid]);

    // ---- fused f_phi: last CTA of this image runs the head inline ----
    __threadfence();
    __syncthreads();
    if (tid == 0) {
        int old = atomicAdd(&cnt[b], 1);
        lastFlag = (old == NN/2 - 1);          // 32 CTAs per image
    }
    __syncthreads();
    if (lastFlag) {
        __threadfence();
        float* ga = colsum;          // reuse SMEM
        float* gb = biasS;
        if (tid < HID) {
            ga[tid] = gsum[(size_t)b*HID + tid] * (1.0f / (NN*NN));
            gsum[(size_t)b*HID + tid] = 0.f;   // restore invariant
        }
        if (tid >= 256 && tid < 256 + 4*CH) {  // restore BN accumulators
            bnsum_g[tid - 256] = 0.f;
            bnsq_g [tid - 256] = 0.f;
        }
        if (tid == 0) cnt[b] = 0;              // restore counter
        __syncthreads();
        if (tid < HID) {
            float a2 = fb1[tid];
            for (int f = 0; f < HID; f++) a2 += ga[f] * fw1[f*HID + tid];
            gb[tid] = fmaxf(a2, 0.f);
        }
        __syncthreads();
        if (tid < HID) {
            float a2 = fb2[tid];
            for (int f = 0; f < HID; f++) a2 += gb[f] * fw2[f*HID + tid];
            ga[tid] = fmaxf(a2, 0.f);           // safe: layer-1 fully consumed ga
        }
        __syncthreads();
        if (tid < AD) {
            float o = fb3[tid];
            for (int f = 0; f < HID; f++) o += ga[f] * fw3[f*AD + tid];
            out[b*AD + tid] = o;
        }
    }
}

// ---------------------------------------------------------------------------
// Launch
// ---------------------------------------------------------------------------
extern "C" void kernel_launch(void* const* d_in, const int* in_sizes, int n_in,
                              void* d_out, int out_size) {
    (void)in_sizes; (void)n_in; (void)out_size;
    const float* img = (const float*)d_in[0];
    const float* q   = (const float*)d_in[1];
    const float* cw[4] = {(const float*)d_in[2],  (const float*)d_in[6],
                          (const float*)d_in[10], (const float*)d_in[14]};
    const float* cb[4] = {(const float*)d_in[3],  (const float*)d_in[7],
                          (const float*)d_in[11], (const float*)d_in[15]};
    const float* bg[4] = {(const float*)d_in[4],  (const float*)d_in[8],
                          (const float*)d_in[12], (const float*)d_in[16]};
    const float* bb[4] = {(const float*)d_in[5],  (const float*)d_in[9],
                          (const float*)d_in[13], (const float*)d_in[17]};
    const float* gw1 = (const float*)d_in[18]; const float* gb1 = (const float*)d_in[19];
    const float* gw2 = (const float*)d_in[20]; const float* gb2 = (const float*)d_in[21];
    const float* gw3 = (const float*)d_in[22]; const float* gb3 = (const float*)d_in[23];
    const float* gw4 = (const float*)d_in[24]; const float* gb4 = (const float*)d_in[25];
    const float* fw1 = (const float*)d_in[26]; const float* fb1 = (const float*)d_in[27];
    const float* fw2 = (const float*)d_in[28]; const float* fb2 = (const float*)d_in[29];
    const float* fw3 = (const float*)d_in[30]; const float* fb3 = (const float*)d_in[31];
    float* out = (float*)d_out;

    float *x1, *x2, *x3, *x4, *u, *v, *s, *gsum, *bnsum, *bnsq;
    uint2* wfp;
    int* cnt;
    cudaGetSymbolAddress((void**)&x1,    g_x1);
    cudaGetSymbolAddress((void**)&x2,    g_x2);
    cudaGetSymbolAddress((void**)&x3,    g_x3);
    cudaGetSymbolAddress((void**)&x4,    g_x4);
    cudaGetSymbolAddress((void**)&u,     g_u);
    cudaGetSymbolAddress((void**)&v,     g_v);
    cudaGetSymbolAddress((void**)&s,     g_s);
    cudaGetSymbolAddress((void**)&gsum,  g_gsum);
    cudaGetSymbolAddress((void**)&wfp,   g_wf);
    cudaGetSymbolAddress((void**)&bnsum, g_bnsum);
    cudaGetSymbolAddress((void**)&bnsq,  g_bnsq);
    cudaGetSymbolAddress((void**)&cnt,   g_cnt);

    cudaFuncSetAttribute(rn_mma_kernel,
                         cudaFuncAttributeMaxDynamicSharedMemorySize, DYN_RN);
    cudaFuncSetAttribute(conv_tile_kernel<24,24,64,32,8,6,64*64,true,false>,
                         cudaFuncAttributeMaxDynamicSharedMemorySize, CONVN_DYN);
    cudaFuncSetAttribute(conv_tile_kernel<24,24,32,16,8,6,32*32,true,false>,
                         cudaFuncAttributeMaxDynamicSharedMemorySize, CONVN_DYN);

    // #1: conv1 128->64 (16x16 tiles, 16/img, 256 thr) + wfrag tail  [R12]
    conv_tile_kernel<3,24,128,64,16,24,0,false,true><<<BSZ*16, 256, CONV1_DYN>>>(
        img, cw[0], cb[0], nullptr, nullptr, nullptr, nullptr,
        x1, bnsum+0, bnsq+0, gw2, gw3, gw4, wfp);
    // #2: conv2 64->32 (8x8 tiles, 16/img, 256 thr, BN1 inline)      [R12]
    conv_tile_kernel<24,24,64,32,8,6,64*64,true,false><<<BSZ*16, 256, CONVN_DYN>>>(
        x1, cw[1], cb[1], bnsum+0, bnsq+0, bg[0], bb[0],
        x2, bnsum+CH, bnsq+CH, nullptr, nullptr, nullptr, nullptr);
    // #3: conv3 32->16 (8x8 tiles, 4/img, 256 thr)                   [R12]
    conv_tile_kernel<24,24,32,16,8,6,32*32,true,false><<<BSZ*4, 256, CONVN_DYN>>>(
        x2, cw[2], cb[2], bnsum+CH, bnsq+CH, bg[1], bb[1],
        x3, bnsum+2*CH, bnsq+2*CH, nullptr, nullptr, nullptr, nullptr);
    // #4: conv4 16->8 (4x4 tiles, 4/img, 192 thr)                    [R12]
    conv_tile_kernel<24,24,16,8,4,2,16*16,true,false><<<BSZ*4, 192, CONV4_DYN>>>(
        x3, cw[3], cb[3], bnsum+2*CH, bnsq+2*CH, bg[2], bb[2],
        x4, bnsum+3*CH, bnsq+3*CH, nullptr, nullptr, nullptr, nullptr);
    // #5: u/v (+s), BN4 finalize inline — 2 objects/block            [R12]
    uv_kernel<<<BSZ*NN/2, 512>>>(x4, bnsum+3*CH, bnsq+3*CH, bg[3], bb[3],
                                 q, gw1, gb1, u, v, s);
    // #6: the core + fused f_phi tail (last kernel)
    rn_mma_kernel<<<BSZ*NN/2, 512, DYN_RN>>>(
        u, v, s, gsum, wfp, gb2, gb3, gb4,
        fw1, fb1, fw2, fb2, fw3, fb3, out, cnt, bnsum, bnsq);
}

// round 15
// speedup vs baseline: 1.0998x; 1.0998x over previous
#include <cuda_runtime.h>
#include <cuda_fp16.h>
#include <math.h>
#include <stdint.h>

// ---------------------------------------------------------------------------
// Problem constants
// ---------------------------------------------------------------------------
#define BSZ   64
#define IMG   128
#define CH    24
#define QD    11
#define AD    10
#define NN    64      // objects per image (8x8)
#define FD    26      // CH + 2 coords
#define HID   256
#define EPSV  1e-5f

// rn_mma geometry (fp16) — proven 512-thread configuration (R10/R12, 590us)
#define M_CTA     128
#define SA        264            // half-element stride
#define WSLAB_B   32768
#define N_SLABS   12
#define DYN_RN    (2*WSLAB_B + M_CTA*SA*2)   // 133120

// ---------------------------------------------------------------------------
// Scratch
// ---------------------------------------------------------------------------
__device__ float  g_x1[BSZ*CH*64*64];
__device__ float  g_x2[BSZ*CH*32*32];
__device__ float  g_x3[BSZ*CH*16*16];
__device__ float  g_x4[BSZ*CH*8*8];
__device__ float  g_u [BSZ*NN*HID];
__device__ float  g_v [BSZ*NN*HID];
__device__ float  g_s [BSZ*HID];
__device__ float  g_gsum[BSZ*HID];    // zero-init at load; re-zeroed by fphi
__device__ uint2  g_wf[3*16*32*32];
__device__ float  g_bnsum[4*CH];      // zero-init at load; re-zeroed by fphi
__device__ float  g_bnsq [4*CH];

// ---------------------------------------------------------------------------
// Helpers
// ---------------------------------------------------------------------------
__device__ __forceinline__ uint32_t smem_u32(const void* p) {
    uint32_t a;
    asm("{ .reg .u64 t; cvta.to.shared.u64 t, %1; cvt.u32.u64 %0, t; }"
        : "=r"(a) : "l"(p));
    return a;
}
__device__ __forceinline__ void mma_f16(float* c, const uint32_t* a,
                                        uint32_t b0, uint32_t b1) {
    asm volatile(
        "mma.sync.aligned.m16n8k16.row.col.f32.f16.f16.f32 "
        "{%0,%1,%2,%3}, {%4,%5,%6,%7}, {%8,%9}, {%0,%1,%2,%3};"
        : "+f"(c[0]), "+f"(c[1]), "+f"(c[2]), "+f"(c[3])
        : "r"(a[0]), "r"(a[1]), "r"(a[2]), "r"(a[3]), "r"(b0), "r"(b1));
}
__device__ __forceinline__ void cp16(uint32_t dst, const void* src) {
    asm volatile("cp.async.cg.shared.global [%0], [%1], 16;"
                 :: "r"(dst), "l"(__cvta_generic_to_global(src)) : "memory");
}
#define CP_COMMIT() asm volatile("cp.async.commit_group;" ::: "memory")
#define CP_WAIT1()  asm volatile("cp.async.wait_group 1;" ::: "memory")
#define CP_WAIT0()  asm volatile("cp.async.wait_group 0;" ::: "memory")

__device__ __forceinline__ uint32_t pack_h2(float lo, float hi) {
    __half2 h = __floats2half2_rn(lo, hi);
    return *(uint32_t*)&h;
}

// ---------------------------------------------------------------------------
// Tiled conv (k=3,s=2,p=1) + inline input-BN + bias + ReLU + channel stats.
// Big buffers in DYNAMIC smem (planes, then weights at aligned offset).
// ---------------------------------------------------------------------------
template<int CI, int CO, int HIN, int HOUT, int TILE, int CPG, int HW_IN,
         bool APPLY, bool WFRAG>
__global__ void __launch_bounds__(TILE*TILE*CO/CPG)
conv_tile_kernel(const float* __restrict__ in,
                 const float* __restrict__ w,
                 const float* __restrict__ bias,
                 const float* __restrict__ sum_in,
                 const float* __restrict__ sq_in,
                 const float* __restrict__ bg_in,
                 const float* __restrict__ bb_in,
                 float* __restrict__ out,
                 float* __restrict__ sum_g,
                 float* __restrict__ sq_g,
                 const float* __restrict__ gw2,
                 const float* __restrict__ gw3,
                 const float* __restrict__ gw4,
                 uint2* __restrict__ wf) {
    constexpr int PW     = 2*TILE + 1;
    constexpr int PSZ    = PW*PW;
    constexpr int NPIX   = TILE*TILE;
    constexpr int NG     = CO/CPG;
    constexpr int NT     = NPIX*NG;
    constexpr int PL_PAD = (CI*PSZ + 3) & ~3;
    extern __shared__ float plS[];                   // planes + weights
    float* wS = plS + PL_PAD;                        // CI*CO*12 floats
    __shared__ float bS[CO];
    __shared__ float sci[CI], shi[CI];
    __shared__ float csum[CO], csq[CO];

    const int tid = threadIdx.x;
    for (int i = tid; i < CI*CO*9; i += NT) {
        int cico = i / 9, k = i - cico*9;
        int co = cico / CI, ci = cico - co*CI;
        wS[(ci*CO + co)*12 + k] = w[i];
    }
    if (tid < CO) { bS[tid] = bias[tid]; csum[tid] = 0.f; csq[tid] = 0.f; }
    if (tid < CI) {
        if (APPLY) {
            float cnt = (float)(BSZ * HW_IN);
            float m   = sum_in[tid] / cnt;
            float var = sq_in[tid] / cnt - m * m;
            float inv = rsqrtf(var + EPSV);
            float sc  = bg_in[tid] * inv;
            sci[tid] = sc;
            shi[tid] = bb_in[tid] - m * sc;
        } else { sci[tid] = 1.f; shi[tid] = 0.f; }
    }
    __syncthreads();

    constexpr int TPS = HOUT / TILE;
    const int bx = blockIdx.x;
    const int b  = bx / (TPS*TPS);
    const int tr = bx - b*(TPS*TPS);
    const int ty = (tr / TPS) * TILE;
    const int tx = (tr - (tr / TPS)*TPS) * TILE;
    const int iy0 = ty*2 - 1;
    const int ix0 = tx*2 - 1;

    for (int i = tid; i < CI*PSZ; i += NT) {
        int ci = i / PSZ;
        int r  = i - ci*PSZ;
        int ry = r / PW, rx = r - ry*PW;
        int gy = iy0 + ry, gx = ix0 + rx;
        float v = 0.f;
        if (gy >= 0 && gy < HIN && gx >= 0 && gx < HIN)
            v = in[((size_t)(b*CI + ci)*HIN + gy)*HIN + gx] * sci[ci] + shi[ci];
        plS[i] = v;
    }
    __syncthreads();

    const int pix = tid & (NPIX - 1);
    const int cg  = tid / NPIX;
    const int py  = pix / TILE;
    const int px  = pix - py*TILE;
    const int co0 = cg * CPG;

    float acc[CPG];
    #pragma unroll
    for (int cc = 0; cc < CPG; cc++) acc[cc] = 0.f;

    #pragma unroll 2
    for (int ci = 0; ci < CI; ci++) {
        const float* pl = plS + ci*PSZ + (2*py)*PW + 2*px;
        float win[9];
        #pragma unroll
        for (int dy = 0; dy < 3; dy++) {
            win[dy*3+0] = pl[dy*PW+0];
            win[dy*3+1] = pl[dy*PW+1];
            win[dy*3+2] = pl[dy*PW+2];
        }
        #pragma unroll
        for (int cc = 0; cc < CPG; cc++) {
            const float* wp = &wS[(ci*CO + co0 + cc)*12];
            const float4 w0 = *(const float4*)wp;
            const float4 w1 = *(const float4*)(wp + 4);
            const float  w8 = wp[8];
            acc[cc] += win[0]*w0.x + win[1]*w0.y + win[2]*w0.z
                     + win[3]*w0.w + win[4]*w1.x + win[5]*w1.y
                     + win[6]*w1.z + win[7]*w1.w + win[8]*w8;
        }
    }

    // epilogue: bias + relu + store + channel stats.
    constexpr int RW = (NPIX < 32) ? NPIX : 32;
    const int lane = tid & 31;
    #pragma unroll
    for (int cc = 0; cc < CPG; cc++) {
        int co = co0 + cc;
        float val = fmaxf(acc[cc] + bS[co], 0.f);
        out[((size_t)(b*CO + co)*HOUT + ty + py)*HOUT + tx + px] = val;
        float s = val, s2 = val*val;
        #pragma unroll
        for (int off = RW/2; off > 0; off >>= 1) {
            s  += __shfl_xor_sync(0xFFFFFFFFu, s,  off);
            s2 += __shfl_xor_sync(0xFFFFFFFFu, s2, off);
        }
        if ((lane & (RW - 1)) == 0) {
            atomicAdd(&csum[co], s);
            atomicAdd(&csq [co], s2);
        }
    }
    __syncthreads();
    if (tid < CO) {
        atomicAdd(&sum_g[tid], csum[tid]);
        atomicAdd(&sq_g [tid], csq [tid]);
    }

    if (WFRAG) {
        int gidx = blockIdx.x * NT + tid;
        if (gidx < 3*16384) {
            int l  = gidx >> 14;
            int r  = gidx & 16383;
            int k  = r >> 10;
            int jg = (r >> 5) & 31;
            int t  = r & 31;
            const float* g = (l == 0) ? gw2 : (l == 1) ? gw3 : gw4;
            int n  = jg*8 + (t >> 2);
            int kk = k*16 + 2*(t & 3);
            uint2 val;
            val.x = pack_h2(g[(size_t)kk*HID + n],     g[(size_t)(kk+1)*HID + n]);
            val.y = pack_h2(g[(size_t)(kk+8)*HID + n], g[(size_t)(kk+9)*HID + n]);
            wf[gidx] = val;
        }
    }
}

// dynamic smem sizes per instantiation
#define CONV1_DYN ((((3*33*33 + 3) & ~3) + 3*24*12) * 4)     // 16528
#define CONVN_DYN ((((24*17*17 + 3) & ~3) + 24*24*12) * 4)   // 55392
#define CONV4_DYN ((((24*9*9 + 3) & ~3) + 24*24*12) * 4)     // 35424 (<48KB)

// ---------------------------------------------------------------------------
// Launch #5: layer-1 factorization — 2 objects per block (512 thr),
// inline BN4 finalize; blocks handling n==0 also compute s.
// ---------------------------------------------------------------------------
__global__ void __launch_bounds__(512)
uv_kernel(const float* __restrict__ x4,
          const float* __restrict__ bnsum4,
          const float* __restrict__ bnsq4,
          const float* __restrict__ bg4,
          const float* __restrict__ bb4,
          const float* __restrict__ q,
          const float* __restrict__ gw1,
          const float* __restrict__ gb1,
          float* __restrict__ u, float* __restrict__ v,
          float* __restrict__ s) {
    __shared__ float o[2][FD];
    __shared__ float qv[QD];
    const int tid = threadIdx.x;
    const int sub = tid >> 8;
    const int c   = tid & 255;
    const int bn0 = blockIdx.x * 2;
    const int bn  = bn0 + sub;
    const int b   = bn >> 6, n = bn & 63;

    if (tid < 2*CH) {
        int ss = tid / CH, cc = tid - ss*CH;
        int bb_ = (bn0 + ss) >> 6, nn = (bn0 + ss) & 63;
        float cnt = (float)(BSZ * 64);
        float m   = bnsum4[cc] / cnt;
        float var = bnsq4[cc] / cnt - m * m;
        float inv = rsqrtf(var + EPSV);
        float sc  = bg4[cc] * inv;
        float sh  = bb4[cc] - m * sc;
        o[ss][cc] = x4[(size_t)(bb_*CH + cc)*64 + nn] * sc + sh;
    } else if (tid >= 256 && tid < 256 + 2) {
        int ss = tid - 256;
        int nn = (bn0 + ss) & 63;
        o[ss][CH]   = (float)(nn >> 3) * 0.125f;
        o[ss][CH+1] = (float)(nn & 7)  * 0.125f;
    } else if (tid >= 300 && tid < 300 + QD) {
        qv[tid - 300] = q[(bn0 >> 6)*QD + (tid - 300)];
    }
    __syncthreads();

    float us = 0.f, vs = 0.f;
    #pragma unroll
    for (int f = 0; f < FD; f++) {
        float ov = o[sub][f];
        us += ov * gw1[f*HID + c];
        vs += ov * gw1[(FD + f)*HID + c];
    }
    u[(size_t)bn*HID + c] = us;
    v[(size_t)bn*HID + c] = vs;

    if (n == 0 && sub == 0) {
        float sa = gb1[c];
        #pragma unroll
        for (int t = 0; t < QD; t++)
            sa += qv[t] * gw1[(2*FD + t)*HID + c];
        s[(size_t)b*HID + c] = sa;
    }
}

// ---------------------------------------------------------------------------
// Launch #6: tensor-core relational core — R10-proven 512-thread version.
// ---------------------------------------------------------------------------
__global__ void __launch_bounds__(512, 1)
rn_mma_kernel(const float* __restrict__ u, const float* __restrict__ v,
              const float* __restrict__ sb, float* __restrict__ gsum,
              const uint2* __restrict__ wf,
              const float* __restrict__ gb2, const float* __restrict__ gb3,
              const float* __restrict__ gb4) {
    extern __shared__ char dyn[];
    __half* hAh = (__half*)(dyn + 2*WSLAB_B);
    const uint2* wbuf2 = (const uint2*)dyn;
    const uint32_t wsm = smem_u32(dyn);
    __shared__ float biasS[3*HID];
    __shared__ float colsum[HID];

    const int tid  = threadIdx.x;
    const int lane = tid & 31;
    const int warp = tid >> 5;
    const int mg   = warp & 3;
    const int ng   = warp >> 2;
    const int tig  = lane & 3;

    for (int i = tid; i < HID; i += 512) {
        biasS[i]         = gb2[i];
        biasS[HID + i]   = gb3[i];
        biasS[2*HID + i] = gb4[i];
    }
    if (tid < HID) colsum[tid] = 0.f;

    const int b  = blockIdx.x >> 5;
    const int i0 = (blockIdx.x & 31) * 2;
    {
        const int row = tid >> 2;
        const int c0  = (tid & 3) * 64;
        const int ii  = i0 + (row >> 6);
        const int jj  = row & 63;
        const float* up = u  + (size_t)(b*NN + ii) * HID;
        const float* vp = v  + (size_t)(b*NN + jj) * HID;
        const float* sp = sb + (size_t)b * HID;
        #pragma unroll
        for (int f = 0; f < 8; f++) {
            int c = c0 + f*8;
            float4 u0 = *(const float4*)(up + c);
            float4 v0 = *(const float4*)(vp + c);
            float4 s0 = *(const float4*)(sp + c);
            float4 u1 = *(const float4*)(up + c + 4);
            float4 v1 = *(const float4*)(vp + c + 4);
            float4 s1 = *(const float4*)(sp + c + 4);
            uint4 hq;
            hq.x = pack_h2(fmaxf(u0.x+v0.x+s0.x, 0.f), fmaxf(u0.y+v0.y+s0.y, 0.f));
            hq.y = pack_h2(fmaxf(u0.z+v0.z+s0.z, 0.f), fmaxf(u0.w+v0.w+s0.w, 0.f));
            hq.z = pack_h2(fmaxf(u1.x+v1.x+s1.x, 0.f), fmaxf(u1.y+v1.y+s1.y, 0.f));
            hq.w = pack_h2(fmaxf(u1.z+v1.z+s1.z, 0.f), fmaxf(u1.w+v1.w+s1.w, 0.f));
            *(uint4*)(hAh + row*SA + c) = hq;
        }
    }

    {
        const char* src = (const char*)wf;
        #pragma unroll
        for (int i = 0; i < 4; i++)
            cp16(wsm + (i*512 + tid)*16, src + (i*512 + tid)*16);
        CP_COMMIT();
    }

    float acc[2][8][4];

    #pragma unroll 1
    for (int sl = 0; sl < N_SLABS; sl++) {
        const int l   = sl >> 2;
        const int cur = sl & 1;
        __syncthreads();
        if (sl + 1 < N_SLABS) {
            const char* src = (const char*)wf + (size_t)(sl + 1) * WSLAB_B;
            uint32_t dst = wsm + (cur ^ 1) * WSLAB_B;
            #pragma unroll
            for (int i = 0; i < 4; i++)
                cp16(dst + (i*512 + tid)*16, src + (i*512 + tid)*16);
            CP_COMMIT();
            CP_WAIT1();
        } else {
            CP_WAIT0();
        }
        __syncthreads();

        if ((sl & 3) == 0) {
            #pragma unroll
            for (int mt = 0; mt < 2; mt++)
                #pragma unroll
                for (int j = 0; j < 8; j++)
                    #pragma unroll
                    for (int c = 0; c < 4; c++)
                        acc[mt][j][c] = 0.f;
        }

        const uint2* wslab = wbuf2 + cur * (WSLAB_B/8);
        const int kbase = (sl & 3) * 4;
        #pragma unroll
        for (int kk = 0; kk < 4; kk++) {
            const int kcol = (kbase + kk) * 16;
            uint32_t a[2][4];
            #pragma unroll
            for (int mt = 0; mt < 2; mt++) {
                int rA = mg*32 + mt*16 + (lane >> 2);
                const __half* base = hAh + rA*SA + kcol + 2*tig;
                a[mt][0] = *(const uint32_t*)(base);
                a[mt][1] = *(const uint32_t*)(base + 8*SA);
                a[mt][2] = *(const uint32_t*)(base + 8);
                a[mt][3] = *(const uint32_t*)(base + 8*SA + 8);
            }
            #pragma unroll
            for (int j = 0; j < 8; j++) {
                uint2 bb = wslab[(kk*32 + (ng*8 + j))*32 + lane];
                mma_f16(acc[0][j], a[0], bb.x, bb.y);
                mma_f16(acc[1][j], a[1], bb.x, bb.y);
            }
        }

        if ((sl & 3) == 3) {
            __syncthreads();
            if (l < 2) {
                const float* bl = biasS + l*HID;
                #pragma unroll
                for (int mt = 0; mt < 2; mt++) {
                    int rA = mg*32 + mt*16 + (lane >> 2);
                    #pragma unroll
                    for (int j = 0; j < 8; j++) {
                        int col = ng*64 + j*8 + 2*tig;
                        float b0 = bl[col], b1 = bl[col+1];
                        uint32_t lo = pack_h2(fmaxf(acc[mt][j][0] + b0, 0.f),
                                              fmaxf(acc[mt][j][1] + b1, 0.f));
                        uint32_t hi = pack_h2(fmaxf(acc[mt][j][2] + b0, 0.f),
                                              fmaxf(acc[mt][j][3] + b1, 0.f));
                        *(uint32_t*)(hAh + rA*SA + col)     = lo;
                        *(uint32_t*)(hAh + (rA+8)*SA + col) = hi;
                    }
                }
                __syncthreads();
            } else {
                const float* bl = biasS + 2*HID;
                #pragma unroll
                for (int j = 0; j < 8; j++) {
                    int col = ng*64 + j*8 + 2*tig;
                    float b0 = bl[col], b1 = bl[col+1];
                    float s0 = 0.f, s1 = 0.f;
                    #pragma unroll
                    for (int mt = 0; mt < 2; mt++) {
                        s0 += fmaxf(acc[mt][j][0] + b0, 0.f)
                            + fmaxf(acc[mt][j][2] + b0, 0.f);
                        s1 += fmaxf(acc[mt][j][1] + b1, 0.f)
                            + fmaxf(acc[mt][j][3] + b1, 0.f);
                    }
                    #pragma unroll
                    for (int off = 4; off < 32; off <<= 1) {
                        s0 += __shfl_xor_sync(0xFFFFFFFFu, s0, off);
                        s1 += __shfl_xor_sync(0xFFFFFFFFu, s1, off);
                    }
                    if (lane < 4) {
                        atomicAdd(&colsum[col],     s0);
                        atomicAdd(&colsum[col + 1], s1);
                    }
                }
            }
        }
    }

    __syncthreads();
    if (tid < HID) atomicAdd(&gsum[b*HID + tid], colsum[tid]);
}

// ---------------------------------------------------------------------------
// Launch #7: f_phi + restore accumulator invariant (zero gsum/bn arrays)
// ---------------------------------------------------------------------------
__global__ void fphi_kernel(float* __restrict__ gsum,
                            float* __restrict__ bnsum, float* __restrict__ bnsq,
                            const float* __restrict__ fw1, const float* __restrict__ fb1,
                            const float* __restrict__ fw2, const float* __restrict__ fb2,
                            const float* __restrict__ fw3, const float* __restrict__ fb3,
                            float* __restrict__ out) {
    __shared__ float ga[HID], gb[HID];
    int b = blockIdx.x, tid = threadIdx.x;
    ga[tid] = gsum[b*HID + tid] * (1.0f / (NN*NN));
    gsum[b*HID + tid] = 0.f;
    if (b == 0 && tid < 4*CH) { bnsum[tid] = 0.f; bnsq[tid] = 0.f; }
    __syncthreads();
    float acc = fb1[tid];
    for (int f = 0; f < HID; f++) acc += ga[f] * fw1[f*HID + tid];
    gb[tid] = fmaxf(acc, 0.f);
    __syncthreads();
    acc = fb2[tid];
    for (int f = 0; f < HID; f++) acc += gb[f] * fw2[f*HID + tid];
    ga[tid] = fmaxf(acc, 0.f);
    __syncthreads();
    if (tid < AD) {
        float o = fb3[tid];
        for (int f = 0; f < HID; f++) o += ga[f] * fw3[f*AD + tid];
        out[b*AD + tid] = o;
    }
}

// ---------------------------------------------------------------------------
// Launch
// ---------------------------------------------------------------------------
extern "C" void kernel_launch(void* const* d_in, const int* in_sizes, int n_in,
                              void* d_out, int out_size) {
    (void)in_sizes; (void)n_in; (void)out_size;
    const float* img = (const float*)d_in[0];
    const float* q   = (const float*)d_in[1];
    const float* cw[4] = {(const float*)d_in[2],  (const float*)d_in[6],
                          (const float*)d_in[10], (const float*)d_in[14]};
    const float* cb[4] = {(const float*)d_in[3],  (const float*)d_in[7],
                          (const float*)d_in[11], (const float*)d_in[15]};
    const float* bg[4] = {(const float*)d_in[4],  (const float*)d_in[8],
                          (const float*)d_in[12], (const float*)d_in[16]};
    const float* bb[4] = {(const float*)d_in[5],  (const float*)d_in[9],
                          (const float*)d_in[13], (const float*)d_in[17]};
    const float* gw1 = (const float*)d_in[18]; const float* gb1 = (const float*)d_in[19];
    const float* gw2 = (const float*)d_in[20]; const float* gb2 = (const float*)d_in[21];
    const float* gw3 = (const float*)d_in[22]; const float* gb3 = (const float*)d_in[23];
    const float* gw4 = (const float*)d_in[24]; const float* gb4 = (const float*)d_in[25];
    const float* fw1 = (const float*)d_in[26]; const float* fb1 = (const float*)d_in[27];
    const float* fw2 = (const float*)d_in[28]; const float* fb2 = (const float*)d_in[29];
    const float* fw3 = (const float*)d_in[30]; const float* fb3 = (const float*)d_in[31];
    float* out = (float*)d_out;

    float *x1, *x2, *x3, *x4, *u, *v, *s, *gsum, *bnsum, *bnsq;
    uint2* wfp;
    cudaGetSymbolAddress((void**)&x1,    g_x1);
    cudaGetSymbolAddress((void**)&x2,    g_x2);
    cudaGetSymbolAddress((void**)&x3,    g_x3);
    cudaGetSymbolAddress((void**)&x4,    g_x4);
    cudaGetSymbolAddress((void**)&u,     g_u);
    cudaGetSymbolAddress((void**)&v,     g_v);
    cudaGetSymbolAddress((void**)&s,     g_s);
    cudaGetSymbolAddress((void**)&gsum,  g_gsum);
    cudaGetSymbolAddress((void**)&wfp,   g_wf);
    cudaGetSymbolAddress((void**)&bnsum, g_bnsum);
    cudaGetSymbolAddress((void**)&bnsq,  g_bnsq);

    cudaFuncSetAttribute(rn_mma_kernel,
                         cudaFuncAttributeMaxDynamicSharedMemorySize, DYN_RN);
    cudaFuncSetAttribute(conv_tile_kernel<24,24,64,32,8,6,64*64,true,false>,
                         cudaFuncAttributeMaxDynamicSharedMemorySize, CONVN_DYN);
    cudaFuncSetAttribute(conv_tile_kernel<24,24,32,16,8,6,32*32,true,false>,
                         cudaFuncAttributeMaxDynamicSharedMemorySize, CONVN_DYN);

    // #1: conv1 128->64 (16x16 tiles, 16/img, 256 thr) + wfrag tail
    conv_tile_kernel<3,24,128,64,16,24,0,false,true><<<BSZ*16, 256, CONV1_DYN>>>(
        img, cw[0], cb[0], nullptr, nullptr, nullptr, nullptr,
        x1, bnsum+0, bnsq+0, gw2, gw3, gw4, wfp);
    // #2: conv2 64->32 (8x8 tiles, 16/img, 256 thr, BN1 inline)
    conv_tile_kernel<24,24,64,32,8,6,64*64,true,false><<<BSZ*16, 256, CONVN_DYN>>>(
        x1, cw[1], cb[1], bnsum+0, bnsq+0, bg[0], bb[0],
        x2, bnsum+CH, bnsq+CH, nullptr, nullptr, nullptr, nullptr);
    // #3: conv3 32->16 (8x8 tiles, 4/img, 256 thr)
    conv_tile_kernel<24,24,32,16,8,6,32*32,true,false><<<BSZ*4, 256, CONVN_DYN>>>(
        x2, cw[2], cb[2], bnsum+CH, bnsq+CH, bg[1], bb[1],
        x3, bnsum+2*CH, bnsq+2*CH, nullptr, nullptr, nullptr, nullptr);
    // #4: conv4 16->8 (4x4 tiles, 4/img, 192 thr)
    conv_tile_kernel<24,24,16,8,4,2,16*16,true,false><<<BSZ*4, 192, CONV4_DYN>>>(
        x3, cw[3], cb[3], bnsum+2*CH, bnsq+2*CH, bg[2], bb[2],
        x4, bnsum+3*CH, bnsq+3*CH, nullptr, nullptr, nullptr, nullptr);
    // #5: u/v (+s), BN4 finalize inline — 2 objects/block
    uv_kernel<<<BSZ*NN/2, 512>>>(x4, bnsum+3*CH, bnsq+3*CH, bg[3], bb[3],
                                 q, gw1, gb1, u, v, s);
    // #6: the core (R10-proven 512-thread version)
    rn_mma_kernel<<<BSZ*NN/2, 512, DYN_RN>>>(u, v, s, gsum, wfp, gb2, gb3, gb4);
    // #7: f_phi + re-zero accumulators
    fphi_kernel<<<BSZ, 256>>>(gsum, bnsum, bnsq,
                              fw1, fb1, fw2, fb2, fw3, fb3, out);
}

// round 16
// speedup vs baseline: 1.1517x; 1.0472x over previous
#include <cuda_runtime.h>
#include <cuda_fp16.h>
#include <math.h>
#include <stdint.h>

// ---------------------------------------------------------------------------
// Problem constants
// ---------------------------------------------------------------------------
#define BSZ   64
#define IMG   128
#define CH    24
#define QD    11
#define AD    10
#define NN    64      // objects per image (8x8)
#define FD    26      // CH + 2 coords
#define HID   256
#define EPSV  1e-5f

// rn_mma geometry (fp16) — proven 512-thread configuration
#define M_CTA     128
#define SA        264            // half-element stride
#define WSLAB_B   32768
#define N_SLABS   12
#define DYN_RN    (2*WSLAB_B + M_CTA*SA*2)   // 133120

// ---------------------------------------------------------------------------
// Scratch
// ---------------------------------------------------------------------------
__device__ float  g_x1[BSZ*CH*64*64];
__device__ float  g_x2[BSZ*CH*32*32];
__device__ float  g_x3[BSZ*CH*16*16];
__device__ float  g_x4[BSZ*CH*8*8];
__device__ float  g_u [BSZ*NN*HID];
__device__ float  g_v [BSZ*NN*HID];   // stores v' = v + s (s folded in)
__device__ float  g_gsum[BSZ*HID];    // zero-init at load; re-zeroed by fphi
__device__ uint2  g_wf[3*16*32*32];
__device__ float  g_bnsum[4*CH];      // zero-init at load; re-zeroed by fphi
__device__ float  g_bnsq [4*CH];

// ---------------------------------------------------------------------------
// Helpers
// ---------------------------------------------------------------------------
__device__ __forceinline__ uint32_t smem_u32(const void* p) {
    uint32_t a;
    asm("{ .reg .u64 t; cvta.to.shared.u64 t, %1; cvt.u32.u64 %0, t; }"
        : "=r"(a) : "l"(p));
    return a;
}
__device__ __forceinline__ void mma_f16(float* c, const uint32_t* a,
                                        uint32_t b0, uint32_t b1) {
    asm volatile(
        "mma.sync.aligned.m16n8k16.row.col.f32.f16.f16.f32 "
        "{%0,%1,%2,%3}, {%4,%5,%6,%7}, {%8,%9}, {%0,%1,%2,%3};"
        : "+f"(c[0]), "+f"(c[1]), "+f"(c[2]), "+f"(c[3])
        : "r"(a[0]), "r"(a[1]), "r"(a[2]), "r"(a[3]), "r"(b0), "r"(b1));
}
__device__ __forceinline__ void cp16(uint32_t dst, const void* src) {
    asm volatile("cp.async.cg.shared.global [%0], [%1], 16;"
                 :: "r"(dst), "l"(__cvta_generic_to_global(src)) : "memory");
}
#define CP_COMMIT() asm volatile("cp.async.commit_group;" ::: "memory")
#define CP_WAIT1()  asm volatile("cp.async.wait_group 1;" ::: "memory")
#define CP_WAIT0()  asm volatile("cp.async.wait_group 0;" ::: "memory")

__device__ __forceinline__ uint32_t pack_h2(float lo, float hi) {
    __half2 h = __floats2half2_rn(lo, hi);
    return *(uint32_t*)&h;
}

// ---------------------------------------------------------------------------
// Tiled conv (k=3,s=2,p=1) + inline input-BN + bias + ReLU + channel stats.
// Big buffers in DYNAMIC smem (planes, then weights at aligned offset).
// ---------------------------------------------------------------------------
template<int CI, int CO, int HIN, int HOUT, int TILE, int CPG, int HW_IN,
         bool APPLY, bool WFRAG>
__global__ void __launch_bounds__(TILE*TILE*CO/CPG)
conv_tile_kernel(const float* __restrict__ in,
                 const float* __restrict__ w,
                 const float* __restrict__ bias,
                 const float* __restrict__ sum_in,
                 const float* __restrict__ sq_in,
                 const float* __restrict__ bg_in,
                 const float* __restrict__ bb_in,
                 float* __restrict__ out,
                 float* __restrict__ sum_g,
                 float* __restrict__ sq_g,
                 const float* __restrict__ gw2,
                 const float* __restrict__ gw3,
                 const float* __restrict__ gw4,
                 uint2* __restrict__ wf) {
    constexpr int PW     = 2*TILE + 1;
    constexpr int PSZ    = PW*PW;
    constexpr int NPIX   = TILE*TILE;
    constexpr int NG     = CO/CPG;
    constexpr int NT     = NPIX*NG;
    constexpr int PL_PAD = (CI*PSZ + 3) & ~3;
    extern __shared__ float plS[];                   // planes + weights
    float* wS = plS + PL_PAD;                        // CI*CO*12 floats
    __shared__ float bS[CO];
    __shared__ float sci[CI], shi[CI];
    __shared__ float csum[CO], csq[CO];

    const int tid = threadIdx.x;
    for (int i = tid; i < CI*CO*9; i += NT) {
        int cico = i / 9, k = i - cico*9;
        int co = cico / CI, ci = cico - co*CI;
        wS[(ci*CO + co)*12 + k] = w[i];
    }
    if (tid < CO) { bS[tid] = bias[tid]; csum[tid] = 0.f; csq[tid] = 0.f; }
    if (tid < CI) {
        if (APPLY) {
            float cnt = (float)(BSZ * HW_IN);
            float m   = sum_in[tid] / cnt;
            float var = sq_in[tid] / cnt - m * m;
            float inv = rsqrtf(var + EPSV);
            float sc  = bg_in[tid] * inv;
            sci[tid] = sc;
            shi[tid] = bb_in[tid] - m * sc;
        } else { sci[tid] = 1.f; shi[tid] = 0.f; }
    }
    __syncthreads();

    constexpr int TPS = HOUT / TILE;
    const int bx = blockIdx.x;
    const int b  = bx / (TPS*TPS);
    const int tr = bx - b*(TPS*TPS);
    const int ty = (tr / TPS) * TILE;
    const int tx = (tr - (tr / TPS)*TPS) * TILE;
    const int iy0 = ty*2 - 1;
    const int ix0 = tx*2 - 1;

    for (int i = tid; i < CI*PSZ; i += NT) {
        int ci = i / PSZ;
        int r  = i - ci*PSZ;
        int ry = r / PW, rx = r - ry*PW;
        int gy = iy0 + ry, gx = ix0 + rx;
        float v = 0.f;
        if (gy >= 0 && gy < HIN && gx >= 0 && gx < HIN)
            v = in[((size_t)(b*CI + ci)*HIN + gy)*HIN + gx] * sci[ci] + shi[ci];
        plS[i] = v;
    }
    __syncthreads();

    const int pix = tid & (NPIX - 1);
    const int cg  = tid / NPIX;
    const int py  = pix / TILE;
    const int px  = pix - py*TILE;
    const int co0 = cg * CPG;

    float acc[CPG];
    #pragma unroll
    for (int cc = 0; cc < CPG; cc++) acc[cc] = 0.f;

    #pragma unroll 2
    for (int ci = 0; ci < CI; ci++) {
        const float* pl = plS + ci*PSZ + (2*py)*PW + 2*px;
        float win[9];
        #pragma unroll
        for (int dy = 0; dy < 3; dy++) {
            win[dy*3+0] = pl[dy*PW+0];
            win[dy*3+1] = pl[dy*PW+1];
            win[dy*3+2] = pl[dy*PW+2];
        }
        #pragma unroll
        for (int cc = 0; cc < CPG; cc++) {
            const float* wp = &wS[(ci*CO + co0 + cc)*12];
            const float4 w0 = *(const float4*)wp;
            const float4 w1 = *(const float4*)(wp + 4);
            const float  w8 = wp[8];
            acc[cc] += win[0]*w0.x + win[1]*w0.y + win[2]*w0.z
                     + win[3]*w0.w + win[4]*w1.x + win[5]*w1.y
                     + win[6]*w1.z + win[7]*w1.w + win[8]*w8;
        }
    }

    // epilogue: bias + relu + store + channel stats.
    constexpr int RW = (NPIX < 32) ? NPIX : 32;
    const int lane = tid & 31;
    #pragma unroll
    for (int cc = 0; cc < CPG; cc++) {
        int co = co0 + cc;
        float val = fmaxf(acc[cc] + bS[co], 0.f);
        out[((size_t)(b*CO + co)*HOUT + ty + py)*HOUT + tx + px] = val;
        float s = val, s2 = val*val;
        #pragma unroll
        for (int off = RW/2; off > 0; off >>= 1) {
            s  += __shfl_xor_sync(0xFFFFFFFFu, s,  off);
            s2 += __shfl_xor_sync(0xFFFFFFFFu, s2, off);
        }
        if ((lane & (RW - 1)) == 0) {
            atomicAdd(&csum[co], s);
            atomicAdd(&csq [co], s2);
        }
    }
    __syncthreads();
    if (tid < CO) {
        atomicAdd(&sum_g[tid], csum[tid]);
        atomicAdd(&sq_g [tid], csq [tid]);
    }

    if (WFRAG) {
        int gidx = blockIdx.x * NT + tid;
        if (gidx < 3*16384) {
            int l  = gidx >> 14;
            int r  = gidx & 16383;
            int k  = r >> 10;
            int jg = (r >> 5) & 31;
            int t  = r & 31;
            const float* g = (l == 0) ? gw2 : (l == 1) ? gw3 : gw4;
            int n  = jg*8 + (t >> 2);
            int kk = k*16 + 2*(t & 3);
            uint2 val;
            val.x = pack_h2(g[(size_t)kk*HID + n],     g[(size_t)(kk+1)*HID + n]);
            val.y = pack_h2(g[(size_t)(kk+8)*HID + n], g[(size_t)(kk+9)*HID + n]);
            wf[gidx] = val;
        }
    }
}

// dynamic smem sizes per instantiation
#define CONV1_DYN ((((3*33*33 + 3) & ~3) + 3*24*12) * 4)     // 16528
#define CONVN_DYN ((((24*17*17 + 3) & ~3) + 24*24*12) * 4)   // 55392
#define CONV4_DYN ((((24*9*9 + 3) & ~3) + 24*24*12) * 4)     // 35424 (<48KB)

// ---------------------------------------------------------------------------
// Launch #5: layer-1 factorization — 2 objects per block (512 thr),
// inline BN4 finalize. s is folded into v: v' = v + s (each block computes
// its image's s redundantly — 11 FMAs/thread).
// ---------------------------------------------------------------------------
__global__ void __launch_bounds__(512)
uv_kernel(const float* __restrict__ x4,
          const float* __restrict__ bnsum4,
          const float* __restrict__ bnsq4,
          const float* __restrict__ bg4,
          const float* __restrict__ bb4,
          const float* __restrict__ q,
          const float* __restrict__ gw1,
          const float* __restrict__ gb1,
          float* __restrict__ u, float* __restrict__ v) {
    __shared__ float o[2][FD];
    __shared__ float qv[QD];
    const int tid = threadIdx.x;
    const int sub = tid >> 8;
    const int c   = tid & 255;
    const int bn0 = blockIdx.x * 2;
    const int bn  = bn0 + sub;

    if (tid < 2*CH) {
        int ss = tid / CH, cc = tid - ss*CH;
        int bb_ = (bn0 + ss) >> 6, nn = (bn0 + ss) & 63;
        float cnt = (float)(BSZ * 64);
        float m   = bnsum4[cc] / cnt;
        float var = bnsq4[cc] / cnt - m * m;
        float inv = rsqrtf(var + EPSV);
        float sc  = bg4[cc] * inv;
        float sh  = bb4[cc] - m * sc;
        o[ss][cc] = x4[(size_t)(bb_*CH + cc)*64 + nn] * sc + sh;
    } else if (tid >= 256 && tid < 256 + 2) {
        int ss = tid - 256;
        int nn = (bn0 + ss) & 63;
        o[ss][CH]   = (float)(nn >> 3) * 0.125f;
        o[ss][CH+1] = (float)(nn & 7)  * 0.125f;
    } else if (tid >= 300 && tid < 300 + QD) {
        qv[tid - 300] = q[(bn0 >> 6)*QD + (tid - 300)];
    }
    __syncthreads();

    float us = 0.f;
    float vs = gb1[c];                 // start v' with bias
    #pragma unroll
    for (int t = 0; t < QD; t++)       // + s (q part)
        vs += qv[t] * gw1[(2*FD + t)*HID + c];
    #pragma unroll
    for (int f = 0; f < FD; f++) {
        float ov = o[sub][f];
        us += ov * gw1[f*HID + c];
        vs += ov * gw1[(FD + f)*HID + c];
    }
    u[(size_t)bn*HID + c] = us;
    v[(size_t)bn*HID + c] = vs;        // v' = v + s + gb1
}

// ---------------------------------------------------------------------------
// Launch #6: tensor-core relational core — R10-proven 512-thread mainloop;
// prologue now reads only u and v' (s folded in at production).
// ---------------------------------------------------------------------------
__global__ void __launch_bounds__(512, 1)
rn_mma_kernel(const float* __restrict__ u, const float* __restrict__ v,
              float* __restrict__ gsum, const uint2* __restrict__ wf,
              const float* __restrict__ gb2, const float* __restrict__ gb3,
              const float* __restrict__ gb4) {
    extern __shared__ char dyn[];
    __half* hAh = (__half*)(dyn + 2*WSLAB_B);
    const uint2* wbuf2 = (const uint2*)dyn;
    const uint32_t wsm = smem_u32(dyn);
    __shared__ float biasS[3*HID];
    __shared__ float colsum[HID];

    const int tid  = threadIdx.x;
    const int lane = tid & 31;
    const int warp = tid >> 5;
    const int mg   = warp & 3;
    const int ng   = warp >> 2;
    const int tig  = lane & 3;

    for (int i = tid; i < HID; i += 512) {
        biasS[i]         = gb2[i];
        biasS[HID + i]   = gb3[i];
        biasS[2*HID + i] = gb4[i];
    }
    if (tid < HID) colsum[tid] = 0.f;

    const int b  = blockIdx.x >> 5;
    const int i0 = (blockIdx.x & 31) * 2;
    {
        const int row = tid >> 2;
        const int c0  = (tid & 3) * 64;
        const int ii  = i0 + (row >> 6);
        const int jj  = row & 63;
        const float* up = u + (size_t)(b*NN + ii) * HID;
        const float* vp = v + (size_t)(b*NN + jj) * HID;
        #pragma unroll
        for (int f = 0; f < 8; f++) {
            int c = c0 + f*8;
            float4 u0 = *(const float4*)(up + c);
            float4 v0 = *(const float4*)(vp + c);
            float4 u1 = *(const float4*)(up + c + 4);
            float4 v1 = *(const float4*)(vp + c + 4);
            uint4 hq;
            hq.x = pack_h2(fmaxf(u0.x+v0.x, 0.f), fmaxf(u0.y+v0.y, 0.f));
            hq.y = pack_h2(fmaxf(u0.z+v0.z, 0.f), fmaxf(u0.w+v0.w, 0.f));
            hq.z = pack_h2(fmaxf(u1.x+v1.x, 0.f), fmaxf(u1.y+v1.y, 0.f));
            hq.w = pack_h2(fmaxf(u1.z+v1.z, 0.f), fmaxf(u1.w+v1.w, 0.f));
            *(uint4*)(hAh + row*SA + c) = hq;
        }
    }

    {
        const char* src = (const char*)wf;
        #pragma unroll
        for (int i = 0; i < 4; i++)
            cp16(wsm + (i*512 + tid)*16, src + (i*512 + tid)*16);
        CP_COMMIT();
    }

    float acc[2][8][4];

    #pragma unroll 1
    for (int sl = 0; sl < N_SLABS; sl++) {
        const int l   = sl >> 2;
        const int cur = sl & 1;
        __syncthreads();
        if (sl + 1 < N_SLABS) {
            const char* src = (const char*)wf + (size_t)(sl + 1) * WSLAB_B;
            uint32_t dst = wsm + (cur ^ 1) * WSLAB_B;
            #pragma unroll
            for (int i = 0; i < 4; i++)
                cp16(dst + (i*512 + tid)*16, src + (i*512 + tid)*16);
            CP_COMMIT();
            CP_WAIT1();
        } else {
            CP_WAIT0();
        }
        __syncthreads();

        if ((sl & 3) == 0) {
            #pragma unroll
            for (int mt = 0; mt < 2; mt++)
                #pragma unroll
                for (int j = 0; j < 8; j++)
                    #pragma unroll
                    for (int c = 0; c < 4; c++)
                        acc[mt][j][c] = 0.f;
        }

        const uint2* wslab = wbuf2 + cur * (WSLAB_B/8);
        const int kbase = (sl & 3) * 4;
        #pragma unroll
        for (int kk = 0; kk < 4; kk++) {
            const int kcol = (kbase + kk) * 16;
            uint32_t a[2][4];
            #pragma unroll
            for (int mt = 0; mt < 2; mt++) {
                int rA = mg*32 + mt*16 + (lane >> 2);
                const __half* base = hAh + rA*SA + kcol + 2*tig;
                a[mt][0] = *(const uint32_t*)(base);
                a[mt][1] = *(const uint32_t*)(base + 8*SA);
                a[mt][2] = *(const uint32_t*)(base + 8);
                a[mt][3] = *(const uint32_t*)(base + 8*SA + 8);
            }
            #pragma unroll
            for (int j = 0; j < 8; j++) {
                uint2 bb = wslab[(kk*32 + (ng*8 + j))*32 + lane];
                mma_f16(acc[0][j], a[0], bb.x, bb.y);
                mma_f16(acc[1][j], a[1], bb.x, bb.y);
            }
        }

        if ((sl & 3) == 3) {
            __syncthreads();
            if (l < 2) {
                const float* bl = biasS + l*HID;
                #pragma unroll
                for (int mt = 0; mt < 2; mt++) {
                    int rA = mg*32 + mt*16 + (lane >> 2);
                    #pragma unroll
                    for (int j = 0; j < 8; j++) {
                        int col = ng*64 + j*8 + 2*tig;
                        float b0 = bl[col], b1 = bl[col+1];
                        uint32_t lo = pack_h2(fmaxf(acc[mt][j][0] + b0, 0.f),
                                              fmaxf(acc[mt][j][1] + b1, 0.f));
                        uint32_t hi = pack_h2(fmaxf(acc[mt][j][2] + b0, 0.f),
                                              fmaxf(acc[mt][j][3] + b1, 0.f));
                        *(uint32_t*)(hAh + rA*SA + col)     = lo;
                        *(uint32_t*)(hAh + (rA+8)*SA + col) = hi;
                    }
                }
                __syncthreads();
            } else {
                const float* bl = biasS + 2*HID;
                #pragma unroll
                for (int j = 0; j < 8; j++) {
                    int col = ng*64 + j*8 + 2*tig;
                    float b0 = bl[col], b1 = bl[col+1];
                    float s0 = 0.f, s1 = 0.f;
                    #pragma unroll
                    for (int mt = 0; mt < 2; mt++) {
                        s0 += fmaxf(acc[mt][j][0] + b0, 0.f)
                            + fmaxf(acc[mt][j][2] + b0, 0.f);
                        s1 += fmaxf(acc[mt][j][1] + b1, 0.f)
                            + fmaxf(acc[mt][j][3] + b1, 0.f);
                    }
                    #pragma unroll
                    for (int off = 4; off < 32; off <<= 1) {
                        s0 += __shfl_xor_sync(0xFFFFFFFFu, s0, off);
                        s1 += __shfl_xor_sync(0xFFFFFFFFu, s1, off);
                    }
                    if (lane < 4) {
                        atomicAdd(&colsum[col],     s0);
                        atomicAdd(&colsum[col + 1], s1);
                    }
                }
            }
        }
    }

    __syncthreads();
    if (tid < HID) atomicAdd(&gsum[b*HID + tid], colsum[tid]);
}

// ---------------------------------------------------------------------------
// Launch #7: f_phi + restore accumulator invariant (zero gsum/bn arrays)
// ---------------------------------------------------------------------------
__global__ void fphi_kernel(float* __restrict__ gsum,
                            float* __restrict__ bnsum, float* __restrict__ bnsq,
                            const float* __restrict__ fw1, const float* __restrict__ fb1,
                            const float* __restrict__ fw2, const float* __restrict__ fb2,
                            const float* __restrict__ fw3, const float* __restrict__ fb3,
                            float* __restrict__ out) {
    __shared__ float ga[HID], gb[HID];
    int b = blockIdx.x, tid = threadIdx.x;
    ga[tid] = gsum[b*HID + tid] * (1.0f / (NN*NN));
    gsum[b*HID + tid] = 0.f;
    if (b == 0 && tid < 4*CH) { bnsum[tid] = 0.f; bnsq[tid] = 0.f; }
    __syncthreads();
    float acc = fb1[tid];
    for (int f = 0; f < HID; f++) acc += ga[f] * fw1[f*HID + tid];
    gb[tid] = fmaxf(acc, 0.f);
    __syncthreads();
    acc = fb2[tid];
    for (int f = 0; f < HID; f++) acc += gb[f] * fw2[f*HID + tid];
    ga[tid] = fmaxf(acc, 0.f);
    __syncthreads();
    if (tid < AD) {
        float o = fb3[tid];
        for (int f = 0; f < HID; f++) o += ga[f] * fw3[f*AD + tid];
        out[b*AD + tid] = o;
    }
}

// ---------------------------------------------------------------------------
// Launch
// ---------------------------------------------------------------------------
extern "C" void kernel_launch(void* const* d_in, const int* in_sizes, int n_in,
                              void* d_out, int out_size) {
    (void)in_sizes; (void)n_in; (void)out_size;
    const float* img = (const float*)d_in[0];
    const float* q   = (const float*)d_in[1];
    const float* cw[4] = {(const float*)d_in[2],  (const float*)d_in[6],
                          (const float*)d_in[10], (const float*)d_in[14]};
    const float* cb[4] = {(const float*)d_in[3],  (const float*)d_in[7],
                          (const float*)d_in[11], (const float*)d_in[15]};
    const float* bg[4] = {(const float*)d_in[4],  (const float*)d_in[8],
                          (const float*)d_in[12], (const float*)d_in[16]};
    const float* bb[4] = {(const float*)d_in[5],  (const float*)d_in[9],
                          (const float*)d_in[13], (const float*)d_in[17]};
    const float* gw1 = (const float*)d_in[18]; const float* gb1 = (const float*)d_in[19];
    const float* gw2 = (const float*)d_in[20]; const float* gb2 = (const float*)d_in[21];
    const float* gw3 = (const float*)d_in[22]; const float* gb3 = (const float*)d_in[23];
    const float* gw4 = (const float*)d_in[24]; const float* gb4 = (const float*)d_in[25];
    const float* fw1 = (const float*)d_in[26]; const float* fb1 = (const float*)d_in[27];
    const float* fw2 = (const float*)d_in[28]; const float* fb2 = (const float*)d_in[29];
    const float* fw3 = (const float*)d_in[30]; const float* fb3 = (const float*)d_in[31];
    float* out = (float*)d_out;

    float *x1, *x2, *x3, *x4, *u, *v, *gsum, *bnsum, *bnsq;
    uint2* wfp;
    cudaGetSymbolAddress((void**)&x1,    g_x1);
    cudaGetSymbolAddress((void**)&x2,    g_x2);
    cudaGetSymbolAddress((void**)&x3,    g_x3);
    cudaGetSymbolAddress((void**)&x4,    g_x4);
    cudaGetSymbolAddress((void**)&u,     g_u);
    cudaGetSymbolAddress((void**)&v,     g_v);
    cudaGetSymbolAddress((void**)&gsum,  g_gsum);
    cudaGetSymbolAddress((void**)&wfp,   g_wf);
    cudaGetSymbolAddress((void**)&bnsum, g_bnsum);
    cudaGetSymbolAddress((void**)&bnsq,  g_bnsq);

    cudaFuncSetAttribute(rn_mma_kernel,
                         cudaFuncAttributeMaxDynamicSharedMemorySize, DYN_RN);
    cudaFuncSetAttribute(conv_tile_kernel<24,24,64,32,8,6,64*64,true,false>,
                         cudaFuncAttributeMaxDynamicSharedMemorySize, CONVN_DYN);
    cudaFuncSetAttribute(conv_tile_kernel<24,24,32,16,8,6,32*32,true,false>,
                         cudaFuncAttributeMaxDynamicSharedMemorySize, CONVN_DYN);

    // #1: conv1 128->64 (16x16 tiles, 16/img, 256 thr) + wfrag tail
    conv_tile_kernel<3,24,128,64,16,24,0,false,true><<<BSZ*16, 256, CONV1_DYN>>>(
        img, cw[0], cb[0], nullptr, nullptr, nullptr, nullptr,
        x1, bnsum+0, bnsq+0, gw2, gw3, gw4, wfp);
    // #2: conv2 64->32 (8x8 tiles, 16/img, 256 thr, BN1 inline)
    conv_tile_kernel<24,24,64,32,8,6,64*64,true,false><<<BSZ*16, 256, CONVN_DYN>>>(
        x1, cw[1], cb[1], bnsum+0, bnsq+0, bg[0], bb[0],
        x2, bnsum+CH, bnsq+CH, nullptr, nullptr, nullptr, nullptr);
    // #3: conv3 32->16 (8x8 tiles, 4/img, 256 thr)
    conv_tile_kernel<24,24,32,16,8,6,32*32,true,false><<<BSZ*4, 256, CONVN_DYN>>>(
        x2, cw[2], cb[2], bnsum+CH, bnsq+CH, bg[1], bb[1],
        x3, bnsum+2*CH, bnsq+2*CH, nullptr, nullptr, nullptr, nullptr);
    // #4: conv4 16->8 (4x4 tiles, 4/img, 192 thr)
    conv_tile_kernel<24,24,16,8,4,2,16*16,true,false><<<BSZ*4, 192, CONV4_DYN>>>(
        x3, cw[3], cb[3], bnsum+2*CH, bnsq+2*CH, bg[2], bb[2],
        x4, bnsum+3*CH, bnsq+3*CH, nullptr, nullptr, nullptr, nullptr);
    // #5: u/v' (s + gb1 folded into v'), BN4 finalize inline
    uv_kernel<<<BSZ*NN/2, 512>>>(x4, bnsum+3*CH, bnsq+3*CH, bg[3], bb[3],
                                 q, gw1, gb1, u, v);
    // #6: the core (2-stream prologue)
    rn_mma_kernel<<<BSZ*NN/2, 512, DYN_RN>>>(u, v, gsum, wfp, gb2, gb3, gb4);
    // #7: f_phi + re-zero accumulators
    fphi_kernel<<<BSZ, 256>>>(gsum, bnsum, bnsq,
                              fw1, fb1, fw2, fb2, fw3, fb3, out);
}

// round 17
// speedup vs baseline: 1.2468x; 1.0826x over previous
#include <cuda_runtime.h>
#include <cuda_fp16.h>
#include <math.h>
#include <stdint.h>

// ---------------------------------------------------------------------------
// Problem constants
// ---------------------------------------------------------------------------
#define BSZ   64
#define IMG   128
#define CH    24
#define QD    11
#define AD    10
#define NN    64      // objects per image (8x8)
#define FD    26      // CH + 2 coords
#define HID   256
#define EPSV  1e-5f

// rn_mma geometry (fp16) — proven 512-thread configuration
#define M_CTA     128
#define SA        264            // half-element stride
#define WSLAB_B   32768
#define N_SLABS   12
#define DYN_RN    (2*WSLAB_B + M_CTA*SA*2)   // 133120

// ---------------------------------------------------------------------------
// Scratch
// ---------------------------------------------------------------------------
__device__ float  g_x1[BSZ*CH*64*64];
__device__ float  g_x2[BSZ*CH*32*32];
__device__ float  g_x3[BSZ*CH*16*16];
__device__ float  g_x4[BSZ*CH*8*8];
__device__ __half g_u [BSZ*NN*HID];   // fp16 u
__device__ __half g_v [BSZ*NN*HID];   // fp16 v' = v + s + gb1
__device__ float  g_gsum[BSZ*HID];    // zero-init at load; re-zeroed by fphi
__device__ uint2  g_wf[3*16*32*32];
__device__ float  g_bnsum[4*CH];      // zero-init at load; re-zeroed by fphi
__device__ float  g_bnsq [4*CH];

// ---------------------------------------------------------------------------
// Helpers
// ---------------------------------------------------------------------------
__device__ __forceinline__ uint32_t smem_u32(const void* p) {
    uint32_t a;
    asm("{ .reg .u64 t; cvta.to.shared.u64 t, %1; cvt.u32.u64 %0, t; }"
        : "=r"(a) : "l"(p));
    return a;
}
__device__ __forceinline__ void mma_f16(float* c, const uint32_t* a,
                                        uint32_t b0, uint32_t b1) {
    asm volatile(
        "mma.sync.aligned.m16n8k16.row.col.f32.f16.f16.f32 "
        "{%0,%1,%2,%3}, {%4,%5,%6,%7}, {%8,%9}, {%0,%1,%2,%3};"
        : "+f"(c[0]), "+f"(c[1]), "+f"(c[2]), "+f"(c[3])
        : "r"(a[0]), "r"(a[1]), "r"(a[2]), "r"(a[3]), "r"(b0), "r"(b1));
}
__device__ __forceinline__ void cp16(uint32_t dst, const void* src) {
    asm volatile("cp.async.cg.shared.global [%0], [%1], 16;"
                 :: "r"(dst), "l"(__cvta_generic_to_global(src)) : "memory");
}
#define CP_COMMIT() asm volatile("cp.async.commit_group;" ::: "memory")
#define CP_WAIT1()  asm volatile("cp.async.wait_group 1;" ::: "memory")
#define CP_WAIT0()  asm volatile("cp.async.wait_group 0;" ::: "memory")

__device__ __forceinline__ uint32_t pack_h2(float lo, float hi) {
    __half2 h = __floats2half2_rn(lo, hi);
    return *(uint32_t*)&h;
}

// ---------------------------------------------------------------------------
// Tiled conv (k=3,s=2,p=1) + inline input-BN + bias + ReLU + channel stats.
// Big buffers in DYNAMIC smem (planes, then weights at aligned offset).
// ---------------------------------------------------------------------------
template<int CI, int CO, int HIN, int HOUT, int TILE, int CPG, int HW_IN,
         bool APPLY, bool WFRAG>
__global__ void __launch_bounds__(TILE*TILE*CO/CPG)
conv_tile_kernel(const float* __restrict__ in,
                 const float* __restrict__ w,
                 const float* __restrict__ bias,
                 const float* __restrict__ sum_in,
                 const float* __restrict__ sq_in,
                 const float* __restrict__ bg_in,
                 const float* __restrict__ bb_in,
                 float* __restrict__ out,
                 float* __restrict__ sum_g,
                 float* __restrict__ sq_g,
                 const float* __restrict__ gw2,
                 const float* __restrict__ gw3,
                 const float* __restrict__ gw4,
                 uint2* __restrict__ wf) {
    constexpr int PW     = 2*TILE + 1;
    constexpr int PSZ    = PW*PW;
    constexpr int NPIX   = TILE*TILE;
    constexpr int NG     = CO/CPG;
    constexpr int NT     = NPIX*NG;
    constexpr int PL_PAD = (CI*PSZ + 3) & ~3;
    extern __shared__ float plS[];                   // planes + weights
    float* wS = plS + PL_PAD;                        // CI*CO*12 floats
    __shared__ float bS[CO];
    __shared__ float sci[CI], shi[CI];
    __shared__ float csum[CO], csq[CO];

    const int tid = threadIdx.x;
    for (int i = tid; i < CI*CO*9; i += NT) {
        int cico = i / 9, k = i - cico*9;
        int co = cico / CI, ci = cico - co*CI;
        wS[(ci*CO + co)*12 + k] = w[i];
    }
    if (tid < CO) { bS[tid] = bias[tid]; csum[tid] = 0.f; csq[tid] = 0.f; }
    if (tid < CI) {
        if (APPLY) {
            float cnt = (float)(BSZ * HW_IN);
            float m   = sum_in[tid] / cnt;
            float var = sq_in[tid] / cnt - m * m;
            float inv = rsqrtf(var + EPSV);
            float sc  = bg_in[tid] * inv;
            sci[tid] = sc;
            shi[tid] = bb_in[tid] - m * sc;
        } else { sci[tid] = 1.f; shi[tid] = 0.f; }
    }
    __syncthreads();

    constexpr int TPS = HOUT / TILE;
    const int bx = blockIdx.x;
    const int b  = bx / (TPS*TPS);
    const int tr = bx - b*(TPS*TPS);
    const int ty = (tr / TPS) * TILE;
    const int tx = (tr - (tr / TPS)*TPS) * TILE;
    const int iy0 = ty*2 - 1;
    const int ix0 = tx*2 - 1;

    for (int i = tid; i < CI*PSZ; i += NT) {
        int ci = i / PSZ;
        int r  = i - ci*PSZ;
        int ry = r / PW, rx = r - ry*PW;
        int gy = iy0 + ry, gx = ix0 + rx;
        float v = 0.f;
        if (gy >= 0 && gy < HIN && gx >= 0 && gx < HIN)
            v = in[((size_t)(b*CI + ci)*HIN + gy)*HIN + gx] * sci[ci] + shi[ci];
        plS[i] = v;
    }
    __syncthreads();

    const int pix = tid & (NPIX - 1);
    const int cg  = tid / NPIX;
    const int py  = pix / TILE;
    const int px  = pix - py*TILE;
    const int co0 = cg * CPG;

    float acc[CPG];
    #pragma unroll
    for (int cc = 0; cc < CPG; cc++) acc[cc] = 0.f;

    #pragma unroll 2
    for (int ci = 0; ci < CI; ci++) {
        const float* pl = plS + ci*PSZ + (2*py)*PW + 2*px;
        float win[9];
        #pragma unroll
        for (int dy = 0; dy < 3; dy++) {
            win[dy*3+0] = pl[dy*PW+0];
            win[dy*3+1] = pl[dy*PW+1];
            win[dy*3+2] = pl[dy*PW+2];
        }
        #pragma unroll
        for (int cc = 0; cc < CPG; cc++) {
            const float* wp = &wS[(ci*CO + co0 + cc)*12];
            const float4 w0 = *(const float4*)wp;
            const float4 w1 = *(const float4*)(wp + 4);
            const float  w8 = wp[8];
            acc[cc] += win[0]*w0.x + win[1]*w0.y + win[2]*w0.z
                     + win[3]*w0.w + win[4]*w1.x + win[5]*w1.y
                     + win[6]*w1.z + win[7]*w1.w + win[8]*w8;
        }
    }

    // epilogue: bias + relu + store + channel stats.
    constexpr int RW = (NPIX < 32) ? NPIX : 32;
    const int lane = tid & 31;
    #pragma unroll
    for (int cc = 0; cc < CPG; cc++) {
        int co = co0 + cc;
        float val = fmaxf(acc[cc] + bS[co], 0.f);
        out[((size_t)(b*CO + co)*HOUT + ty + py)*HOUT + tx + px] = val;
        float s = val, s2 = val*val;
        #pragma unroll
        for (int off = RW/2; off > 0; off >>= 1) {
            s  += __shfl_xor_sync(0xFFFFFFFFu, s,  off);
            s2 += __shfl_xor_sync(0xFFFFFFFFu, s2, off);
        }
        if ((lane & (RW - 1)) == 0) {
            atomicAdd(&csum[co], s);
            atomicAdd(&csq [co], s2);
        }
    }
    __syncthreads();
    if (tid < CO) {
        atomicAdd(&sum_g[tid], csum[tid]);
        atomicAdd(&sq_g [tid], csq [tid]);
    }

    if (WFRAG) {
        int gidx = blockIdx.x * NT + tid;
        if (gidx < 3*16384) {
            int l  = gidx >> 14;
            int r  = gidx & 16383;
            int k  = r >> 10;
            int jg = (r >> 5) & 31;
            int t  = r & 31;
            const float* g = (l == 0) ? gw2 : (l == 1) ? gw3 : gw4;
            int n  = jg*8 + (t >> 2);
            int kk = k*16 + 2*(t & 3);
            uint2 val;
            val.x = pack_h2(g[(size_t)kk*HID + n],     g[(size_t)(kk+1)*HID + n]);
            val.y = pack_h2(g[(size_t)(kk+8)*HID + n], g[(size_t)(kk+9)*HID + n]);
            wf[gidx] = val;
        }
    }
}

// dynamic smem sizes per instantiation
#define CONV1_DYN ((((3*33*33 + 3) & ~3) + 3*24*12) * 4)     // 16528
#define CONVN_DYN ((((24*17*17 + 3) & ~3) + 24*24*12) * 4)   // 55392
#define CONV4_DYN ((((24*9*9 + 3) & ~3) + 24*24*12) * 4)     // 35424 (<48KB)

// ---------------------------------------------------------------------------
// Launch #5: layer-1 factorization — 2 objects per block (512 thr),
// inline BN4 finalize; s + gb1 folded into v'; outputs fp16.
// ---------------------------------------------------------------------------
__global__ void __launch_bounds__(512)
uv_kernel(const float* __restrict__ x4,
          const float* __restrict__ bnsum4,
          const float* __restrict__ bnsq4,
          const float* __restrict__ bg4,
          const float* __restrict__ bb4,
          const float* __restrict__ q,
          const float* __restrict__ gw1,
          const float* __restrict__ gb1,
          __half* __restrict__ u, __half* __restrict__ v) {
    __shared__ float o[2][FD];
    __shared__ float qv[QD];
    const int tid = threadIdx.x;
    const int sub = tid >> 8;
    const int c   = tid & 255;
    const int bn0 = blockIdx.x * 2;
    const int bn  = bn0 + sub;

    if (tid < 2*CH) {
        int ss = tid / CH, cc = tid - ss*CH;
        int bb_ = (bn0 + ss) >> 6, nn = (bn0 + ss) & 63;
        float cnt = (float)(BSZ * 64);
        float m   = bnsum4[cc] / cnt;
        float var = bnsq4[cc] / cnt - m * m;
        float inv = rsqrtf(var + EPSV);
        float sc  = bg4[cc] * inv;
        float sh  = bb4[cc] - m * sc;
        o[ss][cc] = x4[(size_t)(bb_*CH + cc)*64 + nn] * sc + sh;
    } else if (tid >= 256 && tid < 256 + 2) {
        int ss = tid - 256;
        int nn = (bn0 + ss) & 63;
        o[ss][CH]   = (float)(nn >> 3) * 0.125f;
        o[ss][CH+1] = (float)(nn & 7)  * 0.125f;
    } else if (tid >= 300 && tid < 300 + QD) {
        qv[tid - 300] = q[(bn0 >> 6)*QD + (tid - 300)];
    }
    __syncthreads();

    float us = 0.f;
    float vs = gb1[c];                 // start v' with bias
    #pragma unroll
    for (int t = 0; t < QD; t++)       // + s (q part)
        vs += qv[t] * gw1[(2*FD + t)*HID + c];
    #pragma unroll
    for (int f = 0; f < FD; f++) {
        float ov = o[sub][f];
        us += ov * gw1[f*HID + c];
        vs += ov * gw1[(FD + f)*HID + c];
    }
    u[(size_t)bn*HID + c] = __float2half_rn(us);
    v[(size_t)bn*HID + c] = __float2half_rn(vs);
}

// ---------------------------------------------------------------------------
// Launch #6: tensor-core relational core — R10-proven 512-thread mainloop;
// slab-0 prefetch issued FIRST; prologue reads fp16 u/v' (2 streams, half bytes).
// ---------------------------------------------------------------------------
__global__ void __launch_bounds__(512, 1)
rn_mma_kernel(const __half* __restrict__ u, const __half* __restrict__ v,
              float* __restrict__ gsum, const uint2* __restrict__ wf,
              const float* __restrict__ gb2, const float* __restrict__ gb3,
              const float* __restrict__ gb4) {
    extern __shared__ char dyn[];
    __half* hAh = (__half*)(dyn + 2*WSLAB_B);
    const uint2* wbuf2 = (const uint2*)dyn;
    const uint32_t wsm = smem_u32(dyn);
    __shared__ float biasS[3*HID];
    __shared__ float colsum[HID];

    const int tid  = threadIdx.x;
    const int lane = tid & 31;
    const int warp = tid >> 5;
    const int mg   = warp & 3;
    const int ng   = warp >> 2;
    const int tig  = lane & 3;

    // ---- weight slab 0 prefetch FIRST (overlaps the h1 prologue) ----
    {
        const char* src = (const char*)wf;
        #pragma unroll
        for (int i = 0; i < 4; i++)
            cp16(wsm + (i*512 + tid)*16, src + (i*512 + tid)*16);
        CP_COMMIT();
    }

    for (int i = tid; i < HID; i += 512) {
        biasS[i]         = gb2[i];
        biasS[HID + i]   = gb3[i];
        biasS[2*HID + i] = gb4[i];
    }
    if (tid < HID) colsum[tid] = 0.f;

    const int b  = blockIdx.x >> 5;
    const int i0 = (blockIdx.x & 31) * 2;
    {
        const int row = tid >> 2;
        const int c0  = (tid & 3) * 64;
        const int ii  = i0 + (row >> 6);
        const int jj  = row & 63;
        const __half* up = u + (size_t)(b*NN + ii) * HID;
        const __half* vp = v + (size_t)(b*NN + jj) * HID;
        const __half2 zero2 = __floats2half2_rn(0.f, 0.f);
        #pragma unroll
        for (int f = 0; f < 8; f++) {
            int c = c0 + f*8;
            uint4 uu = *(const uint4*)(up + c);
            uint4 vv = *(const uint4*)(vp + c);
            const __half2* uh = (const __half2*)&uu;
            const __half2* vh = (const __half2*)&vv;
            uint4 hq;
            __half2 r0 = __hmax2(__hadd2(uh[0], vh[0]), zero2);
            __half2 r1 = __hmax2(__hadd2(uh[1], vh[1]), zero2);
            __half2 r2 = __hmax2(__hadd2(uh[2], vh[2]), zero2);
            __half2 r3 = __hmax2(__hadd2(uh[3], vh[3]), zero2);
            hq.x = *(uint32_t*)&r0;
            hq.y = *(uint32_t*)&r1;
            hq.z = *(uint32_t*)&r2;
            hq.w = *(uint32_t*)&r3;
            *(uint4*)(hAh + row*SA + c) = hq;
        }
    }

    float acc[2][8][4];

    #pragma unroll 1
    for (int sl = 0; sl < N_SLABS; sl++) {
        const int l   = sl >> 2;
        const int cur = sl & 1;
        __syncthreads();
        if (sl + 1 < N_SLABS) {
            const char* src = (const char*)wf + (size_t)(sl + 1) * WSLAB_B;
            uint32_t dst = wsm + (cur ^ 1) * WSLAB_B;
            #pragma unroll
            for (int i = 0; i < 4; i++)
                cp16(dst + (i*512 + tid)*16, src + (i*512 + tid)*16);
            CP_COMMIT();
            CP_WAIT1();
        } else {
            CP_WAIT0();
        }
        __syncthreads();

        if ((sl & 3) == 0) {
            #pragma unroll
            for (int mt = 0; mt < 2; mt++)
                #pragma unroll
                for (int j = 0; j < 8; j++)
                    #pragma unroll
                    for (int c = 0; c < 4; c++)
                        acc[mt][j][c] = 0.f;
        }

        const uint2* wslab = wbuf2 + cur * (WSLAB_B/8);
        const int kbase = (sl & 3) * 4;
        #pragma unroll
        for (int kk = 0; kk < 4; kk++) {
            const int kcol = (kbase + kk) * 16;
            uint32_t a[2][4];
            #pragma unroll
            for (int mt = 0; mt < 2; mt++) {
                int rA = mg*32 + mt*16 + (lane >> 2);
                const __half* base = hAh + rA*SA + kcol + 2*tig;
                a[mt][0] = *(const uint32_t*)(base);
                a[mt][1] = *(const uint32_t*)(base + 8*SA);
                a[mt][2] = *(const uint32_t*)(base + 8);
                a[mt][3] = *(const uint32_t*)(base + 8*SA + 8);
            }
            #pragma unroll
            for (int j = 0; j < 8; j++) {
                uint2 bb = wslab[(kk*32 + (ng*8 + j))*32 + lane];
                mma_f16(acc[0][j], a[0], bb.x, bb.y);
                mma_f16(acc[1][j], a[1], bb.x, bb.y);
            }
        }

        if ((sl & 3) == 3) {
            __syncthreads();
            if (l < 2) {
                const float* bl = biasS + l*HID;
                #pragma unroll
                for (int mt = 0; mt < 2; mt++) {
                    int rA = mg*32 + mt*16 + (lane >> 2);
                    #pragma unroll
                    for (int j = 0; j < 8; j++) {
                        int col = ng*64 + j*8 + 2*tig;
                        float b0 = bl[col], b1 = bl[col+1];
                        uint32_t lo = pack_h2(fmaxf(acc[mt][j][0] + b0, 0.f),
                                              fmaxf(acc[mt][j][1] + b1, 0.f));
                        uint32_t hi = pack_h2(fmaxf(acc[mt][j][2] + b0, 0.f),
                                              fmaxf(acc[mt][j][3] + b1, 0.f));
                        *(uint32_t*)(hAh + rA*SA + col)     = lo;
                        *(uint32_t*)(hAh + (rA+8)*SA + col) = hi;
                    }
                }
                __syncthreads();
            } else {
                const float* bl = biasS + 2*HID;
                #pragma unroll
                for (int j = 0; j < 8; j++) {
                    int col = ng*64 + j*8 + 2*tig;
                    float b0 = bl[col], b1 = bl[col+1];
                    float s0 = 0.f, s1 = 0.f;
                    #pragma unroll
                    for (int mt = 0; mt < 2; mt++) {
                        s0 += fmaxf(acc[mt][j][0] + b0, 0.f)
                            + fmaxf(acc[mt][j][2] + b0, 0.f);
                        s1 += fmaxf(acc[mt][j][1] + b1, 0.f)
                            + fmaxf(acc[mt][j][3] + b1, 0.f);
                    }
                    #pragma unroll
                    for (int off = 4; off < 32; off <<= 1) {
                        s0 += __shfl_xor_sync(0xFFFFFFFFu, s0, off);
                        s1 += __shfl_xor_sync(0xFFFFFFFFu, s1, off);
                    }
                    if (lane < 4) {
                        atomicAdd(&colsum[col],     s0);
                        atomicAdd(&colsum[col + 1], s1);
                    }
                }
            }
        }
    }

    __syncthreads();
    if (tid < HID) atomicAdd(&gsum[b*HID + tid], colsum[tid]);
}

// ---------------------------------------------------------------------------
// Launch #7: f_phi + restore accumulator invariant (zero gsum/bn arrays)
// ---------------------------------------------------------------------------
__global__ void fphi_kernel(float* __restrict__ gsum,
                            float* __restrict__ bnsum, float* __restrict__ bnsq,
                            const float* __restrict__ fw1, const float* __restrict__ fb1,
                            const float* __restrict__ fw2, const float* __restrict__ fb2,
                            const float* __restrict__ fw3, const float* __restrict__ fb3,
                            float* __restrict__ out) {
    __shared__ float ga[HID], gb[HID];
    int b = blockIdx.x, tid = threadIdx.x;
    ga[tid] = gsum[b*HID + tid] * (1.0f / (NN*NN));
    gsum[b*HID + tid] = 0.f;
    if (b == 0 && tid < 4*CH) { bnsum[tid] = 0.f; bnsq[tid] = 0.f; }
    __syncthreads();
    float acc = fb1[tid];
    for (int f = 0; f < HID; f++) acc += ga[f] * fw1[f*HID + tid];
    gb[tid] = fmaxf(acc, 0.f);
    __syncthreads();
    acc = fb2[tid];
    for (int f = 0; f < HID; f++) acc += gb[f] * fw2[f*HID + tid];
    ga[tid] = fmaxf(acc, 0.f);
    __syncthreads();
    if (tid < AD) {
        float o = fb3[tid];
        for (int f = 0; f < HID; f++) o += ga[f] * fw3[f*AD + tid];
        out[b*AD + tid] = o;
    }
}

// ---------------------------------------------------------------------------
// Launch
// ---------------------------------------------------------------------------
extern "C" void kernel_launch(void* const* d_in, const int* in_sizes, int n_in,
                              void* d_out, int out_size) {
    (void)in_sizes; (void)n_in; (void)out_size;
    const float* img = (const float*)d_in[0];
    const float* q   = (const float*)d_in[1];
    const float* cw[4] = {(const float*)d_in[2],  (const float*)d_in[6],
                          (const float*)d_in[10], (const float*)d_in[14]};
    const float* cb[4] = {(const float*)d_in[3],  (const float*)d_in[7],
                          (const float*)d_in[11], (const float*)d_in[15]};
    const float* bg[4] = {(const float*)d_in[4],  (const float*)d_in[8],
                          (const float*)d_in[12], (const float*)d_in[16]};
    const float* bb[4] = {(const float*)d_in[5],  (const float*)d_in[9],
                          (const float*)d_in[13], (const float*)d_in[17]};
    const float* gw1 = (const float*)d_in[18]; const float* gb1 = (const float*)d_in[19];
    const float* gw2 = (const float*)d_in[20]; const float* gb2 = (const float*)d_in[21];
    const float* gw3 = (const float*)d_in[22]; const float* gb3 = (const float*)d_in[23];
    const float* gw4 = (const float*)d_in[24]; const float* gb4 = (const float*)d_in[25];
    const float* fw1 = (const float*)d_in[26]; const float* fb1 = (const float*)d_in[27];
    const float* fw2 = (const float*)d_in[28]; const float* fb2 = (const float*)d_in[29];
    const float* fw3 = (const float*)d_in[30]; const float* fb3 = (const float*)d_in[31];
    float* out = (float*)d_out;

    float *x1, *x2, *x3, *x4, *gsum, *bnsum, *bnsq;
    __half *u, *v;
    uint2* wfp;
    cudaGetSymbolAddress((void**)&x1,    g_x1);
    cudaGetSymbolAddress((void**)&x2,    g_x2);
    cudaGetSymbolAddress((void**)&x3,    g_x3);
    cudaGetSymbolAddress((void**)&x4,    g_x4);
    cudaGetSymbolAddress((void**)&u,     g_u);
    cudaGetSymbolAddress((void**)&v,     g_v);
    cudaGetSymbolAddress((void**)&gsum,  g_gsum);
    cudaGetSymbolAddress((void**)&wfp,   g_wf);
    cudaGetSymbolAddress((void**)&bnsum, g_bnsum);
    cudaGetSymbolAddress((void**)&bnsq,  g_bnsq);

    cudaFuncSetAttribute(rn_mma_kernel,
                         cudaFuncAttributeMaxDynamicSharedMemorySize, DYN_RN);
    cudaFuncSetAttribute(conv_tile_kernel<24,24,64,32,8,6,64*64,true,false>,
                         cudaFuncAttributeMaxDynamicSharedMemorySize, CONVN_DYN);
    cudaFuncSetAttribute(conv_tile_kernel<24,24,32,16,8,6,32*32,true,false>,
                         cudaFuncAttributeMaxDynamicSharedMemorySize, CONVN_DYN);

    // #1: conv1 128->64 (16x16 tiles, 16/img, 256 thr) + wfrag tail
    conv_tile_kernel<3,24,128,64,16,24,0,false,true><<<BSZ*16, 256, CONV1_DYN>>>(
        img, cw[0], cb[0], nullptr, nullptr, nullptr, nullptr,
        x1, bnsum+0, bnsq+0, gw2, gw3, gw4, wfp);
    // #2: conv2 64->32 (8x8 tiles, 16/img, 256 thr, BN1 inline)
    conv_tile_kernel<24,24,64,32,8,6,64*64,true,false><<<BSZ*16, 256, CONVN_DYN>>>(
        x1, cw[1], cb[1], bnsum+0, bnsq+0, bg[0], bb[0],
        x2, bnsum+CH, bnsq+CH, nullptr, nullptr, nullptr, nullptr);
    // #3: conv3 32->16 (8x8 tiles, 4/img, 256 thr)
    conv_tile_kernel<24,24,32,16,8,6,32*32,true,false><<<BSZ*4, 256, CONVN_DYN>>>(
        x2, cw[2], cb[2], bnsum+CH, bnsq+CH, bg[1], bb[1],
        x3, bnsum+2*CH, bnsq+2*CH, nullptr, nullptr, nullptr, nullptr);
    // #4: conv4 16->8 (4x4 tiles, 4/img, 192 thr)
    conv_tile_kernel<24,24,16,8,4,2,16*16,true,false><<<BSZ*4, 192, CONV4_DYN>>>(
        x3, cw[3], cb[3], bnsum+2*CH, bnsq+2*CH, bg[2], bb[2],
        x4, bnsum+3*CH, bnsq+3*CH, nullptr, nullptr, nullptr, nullptr);
    // #5: u/v' (fp16; s + gb1 folded into v'), BN4 finalize inline
    uv_kernel<<<BSZ*NN/2, 512>>>(x4, bnsum+3*CH, bnsq+3*CH, bg[3], bb[3],
                                 q, gw1, gb1, u, v);
    // #6: the core (prefetch-first, fp16 2-stream prologue)
    rn_mma_kernel<<<BSZ*NN/2, 512, DYN_RN>>>(u, v, gsum, wfp, gb2, gb3, gb4);
    // #7: f_phi + re-zero accumulators
    fphi_kernel<<<BSZ, 256>>>(gsum, bnsum, bnsq,
                              fw1, fb1, fw2, fb2, fw3, fb3, out);
}